// round 1
// baseline (speedup 1.0000x reference)
#include <cuda_runtime.h>
#include <math.h>

// ----------------------------------------------------------------------------
// FARGAN vocoder: 64 independent batch rows, 100 frames x 4 subframes of a
// strictly sequential GRU stack. One CTA per batch row runs the whole
// recurrence; conditioning net precomputed for all frames in parallel.
// Weights transposed to K-major (coalesced float4 loads) into device global.
// ----------------------------------------------------------------------------

#define NFRAMES 100
#define NB      64

__device__ __forceinline__ float sigmoidf_(float x) { return 1.0f / (1.0f + expf(-x)); }

// transposed-weight offsets (floats)
enum : int {
  OFF_FW      = 0,
  OFF_FWGLU   = OFF_FW      + 520 * 256,
  OFF_G1IH    = OFF_FWGLU   + 256 * 256,
  OFF_G1HH    = OFF_G1IH    + 384 * 768,
  OFF_G2IH    = OFF_G1HH    + 256 * 768,
  OFF_G2HH    = OFF_G2IH    + 384 * 768,
  OFF_G3IH    = OFF_G2HH    + 256 * 768,
  OFF_G3HH    = OFF_G3IH    + 384 * 768,
  OFF_GLU1    = OFF_G3HH    + 256 * 768,
  OFF_GLU2    = OFF_GLU1    + 256 * 256,
  OFF_GLU3    = OFF_GLU2    + 256 * 256,
  OFF_SKIP    = OFF_GLU3    + 256 * 256,
  OFF_SKIPGLU = OFF_SKIP    + 1152 * 256,
  OFF_OUT     = OFF_SKIPGLU + 256 * 256,
  OFF_C1      = OFF_OUT     + 256 * 64,
  OFF_C2      = OFF_C1      + 336 * 336,
  OFF_C3      = OFF_C2      + 336 * 336,
  WT_TOTAL    = OFF_C3      + 336 * 512
};

__device__ float g_wt[WT_TOTAL];
__device__ float g_cond[NFRAMES * NB * 512];

// ---------------------------------------------------------------------------
// transpose: src[O][I] row-major -> dst[I][O]
__global__ void transpose_k(const float* __restrict__ src, float* __restrict__ dst,
                            int O, int I) {
  int idx = blockIdx.x * blockDim.x + threadIdx.x;
  if (idx < O * I) {
    int i = idx / O;
    int o = idx % O;
    dst[idx] = src[o * I + i];
  }
}

// ---------------------------------------------------------------------------
// GEMV partial: 256 threads = 4 K-chunks x 64 lanesets. Each thread accumulates
// float4 of outputs over its K-chunk. part[4][N]. Caller syncs + combines.
__device__ __forceinline__ void gemv_part(const float* __restrict__ Wt,
                                          const float* __restrict__ xs,
                                          int K, int N, float* part) {
  const int tid = threadIdx.x;
  const int kc  = tid >> 6;
  const int g0  = tid & 63;
  const int Kc  = K >> 2;
  const int G   = N >> 2;
  const float4* __restrict__ W4 = reinterpret_cast<const float4*>(Wt) + (size_t)(kc * Kc) * G;
  const float*  __restrict__ xk = xs + kc * Kc;
  float4* P4 = reinterpret_cast<float4*>(part + kc * N);
  for (int g = g0; g < G; g += 64) {
    float4 acc = make_float4(0.f, 0.f, 0.f, 0.f);
    const float4* wp = W4 + g;
#pragma unroll 4
    for (int k = 0; k < Kc; ++k) {
      const float xv = xk[k];
      const float4 w = wp[(size_t)k * G];
      acc.x = fmaf(xv, w.x, acc.x);
      acc.y = fmaf(xv, w.y, acc.y);
      acc.z = fmaf(xv, w.z, acc.z);
      acc.w = fmaf(xv, w.w, acc.w);
    }
    P4[g] = acc;
  }
}

__device__ __forceinline__ float csum(const float* part, int N, int j) {
  return (part[j] + part[N + j]) + (part[2 * N + j] + part[3 * N + j]);
}

// ---------------------------------------------------------------------------
// conditioning network for all frames (parallel): grid (64 batch, 100 frames)
__global__ __launch_bounds__(256)
void cond_kernel(const float* __restrict__ feat, const float* __restrict__ gf) {
  __shared__ __align__(16) float s_part[4 * 512];
  __shared__ float s_x[336];
  __shared__ float s_y[336];
  const int b = blockIdx.x, f = blockIdx.y, tid = threadIdx.x;

  for (int j = tid; j < 80; j += 256)  s_x[j]      = feat[(b * 80 + j) * NFRAMES + f];
  for (int j = tid; j < 256; j += 256) s_x[80 + j] = gf[b * 256 + j];
  __syncthreads();
  gemv_part(g_wt + OFF_C1, s_x, 336, 336, s_part);
  __syncthreads();
  for (int j = tid; j < 336; j += 256) s_y[j] = tanhf(csum(s_part, 336, j));
  __syncthreads();
  gemv_part(g_wt + OFF_C2, s_y, 336, 336, s_part);
  __syncthreads();
  for (int j = tid; j < 336; j += 256) s_x[j] = tanhf(csum(s_part, 336, j));
  __syncthreads();
  gemv_part(g_wt + OFF_C3, s_x, 336, 512, s_part);
  __syncthreads();
  float* dst = g_cond + (f * NB + b) * 512;
  for (int j = tid; j < 512; j += 256) dst[j] = tanhf(csum(s_part, 512, j));
}

// ---------------------------------------------------------------------------
// helpers for the recurrence (all 256 threads call uniformly)
__device__ __forceinline__ void gru_step(const float* wih_t, const float* whh_t,
                                         float* s_state, const float* s_xin,
                                         float* s_part, float* s_xg, float* s_hg) {
  const int tid = threadIdx.x;
  gemv_part(wih_t, s_xin, 384, 768, s_part);
  __syncthreads();
  for (int j = tid; j < 768; j += 256) s_xg[j] = csum(s_part, 768, j);
  __syncthreads();
  gemv_part(whh_t, s_state, 256, 768, s_part);
  __syncthreads();
  for (int j = tid; j < 768; j += 256) s_hg[j] = csum(s_part, 768, j);
  __syncthreads();
  {
    float r = sigmoidf_(s_xg[tid] + s_hg[tid]);
    float z = sigmoidf_(s_xg[256 + tid] + s_hg[256 + tid]);
    float n = tanhf(s_xg[512 + tid] + r * s_hg[512 + tid]);
    s_state[tid] = (1.f - z) * n + z * s_state[tid];
  }
  __syncthreads();
}

__device__ __forceinline__ void glu_mul(const float* w_t, const float* src,
                                        float* dst, float* s_part) {
  const int tid = threadIdx.x;
  gemv_part(w_t, src, 256, 256, s_part);
  __syncthreads();
  dst[tid] = src[tid] * sigmoidf_(csum(s_part, 256, tid));
  __syncthreads();
}

// ---------------------------------------------------------------------------
// main sequential kernel: one CTA per batch row
__global__ __launch_bounds__(256)
void main_kernel(const float* __restrict__ prev0,
                 const int*   __restrict__ periods,
                 const float* __restrict__ gain_w,
                 const float* __restrict__ gain_b,
                 const float* __restrict__ pg_w,
                 const float* __restrict__ pg_b,
                 float*       __restrict__ outp) {
  __shared__ __align__(16) float s_part[4 * 1152];
  __shared__ float s_x[1152];
  __shared__ float s_xg[768], s_hg[768];
  __shared__ float s_prev[256], s_s1[256], s_s2[256], s_s3[256], s_s4[260];
  __shared__ float s_fw[256], s_fw2[256], s_o1[256], s_o2[256], s_o3[256], s_sk[256];
  __shared__ float s_pl[68], s_psub[64], s_pg[4], s_gain[2], s_out[64];

  const int b = blockIdx.x, tid = threadIdx.x;

  s_prev[tid] = prev0[b * 256 + tid];
  s_s1[tid] = 0.f; s_s2[tid] = 0.f; s_s3[tid] = 0.f;
  s_s4[tid] = 0.f;
  if (tid < 4) s_s4[256 + tid] = 0.f;
  __syncthreads();

  const float gb0 = gain_b[0];

  for (int f = 0; f < NFRAMES; ++f) {
    const int per = periods[b * NFRAMES + f];
    const float* condf = g_cond + (f * NB + b) * 512;

    for (int i = 0; i < 4; ++i) {
      const float* sf = condf + i * 128;

      // ---- gain = exp(sf . gain_w + b) (warp 0)
      if (tid < 32) {
        float d = 0.f;
        for (int k = tid; k < 128; k += 32) d = fmaf(sf[k], gain_w[k], d);
#pragma unroll
        for (int o = 16; o; o >>= 1) d += __shfl_xor_sync(0xffffffffu, d, o);
        if (tid == 0) {
          float g = expf(d + gb0);
          s_gain[0] = g;
          s_gain[1] = 1.0f / (1e-5f + g);
        }
      }
      __syncthreads();
      const float ginv = s_gain[1];

      // ---- pitch-lag gather + scaling; prev_sub
      if (tid < 68) {
        int idx = 256 - per + tid - 2;
        if (idx >= 256) idx -= per;
        s_pl[tid] = s_prev[idx] * ginv;
      } else if (tid >= 128 && tid < 192) {
        s_psub[tid - 128] = s_prev[tid + 64] * ginv;  // prev[192..255]
      }
      __syncthreads();

      // ---- assemble fw input: [sf(128), psub(64), pl(68), s4(260)] = 520
      if (tid < 128)       s_x[tid] = sf[tid];
      else if (tid < 192)  s_x[tid] = s_psub[tid - 128];
      else                 s_x[tid] = s_pl[tid - 192];
      if (tid < 4)         s_x[256 + tid] = s_pl[64 + tid];
      s_x[260 + tid] = s_s4[tid];
      if (tid < 4) s_x[516 + tid] = s_s4[256 + tid];
      __syncthreads();

      // s4 <- sif (copy of x[0:260]); runs alongside fw gemv (both read s_x)
      s_s4[tid] = s_x[tid];
      if (tid < 4) s_s4[256 + tid] = s_x[256 + tid];

      gemv_part(g_wt + OFF_FW, s_x, 520, 256, s_part);
      __syncthreads();
      s_fw[tid] = tanhf(csum(s_part, 256, tid));
      __syncthreads();

      gemv_part(g_wt + OFF_FWGLU, s_fw, 256, 256, s_part);
      __syncthreads();
      s_fw2[tid] = s_fw[tid] * sigmoidf_(csum(s_part, 256, tid));
      __syncthreads();

      // ---- pg (4 warps)
      if (tid < 128) {
        int w = tid >> 5, l = tid & 31;
        float d = 0.f;
        for (int k = l; k < 256; k += 32) d = fmaf(s_fw2[k], pg_w[w * 256 + k], d);
#pragma unroll
        for (int o = 16; o; o >>= 1) d += __shfl_xor_sync(0xffffffffu, d, o);
        if (l == 0) s_pg[w] = sigmoidf_(d + pg_b[w]) + 1e-5f;
      }
      __syncthreads();

      // ---- GRU1
      s_x[tid] = s_fw2[tid];
      if (tid < 64)       s_x[256 + tid] = s_pg[0] * s_pl[2 + tid];
      else if (tid < 128) s_x[256 + tid] = s_psub[tid - 64];
      __syncthreads();
      gru_step(g_wt + OFF_G1IH, g_wt + OFF_G1HH, s_s1, s_x, s_part, s_xg, s_hg);
      glu_mul(g_wt + OFF_GLU1, s_s1, s_o1, s_part);

      // ---- GRU2
      s_x[tid] = s_o1[tid];
      if (tid < 64)       s_x[256 + tid] = s_pg[1] * s_pl[2 + tid];
      else if (tid < 128) s_x[256 + tid] = s_psub[tid - 64];
      __syncthreads();
      gru_step(g_wt + OFF_G2IH, g_wt + OFF_G2HH, s_s2, s_x, s_part, s_xg, s_hg);
      glu_mul(g_wt + OFF_GLU2, s_s2, s_o2, s_part);

      // ---- GRU3
      s_x[tid] = s_o2[tid];
      if (tid < 64)       s_x[256 + tid] = s_pg[2] * s_pl[2 + tid];
      else if (tid < 128) s_x[256 + tid] = s_psub[tid - 64];
      __syncthreads();
      gru_step(g_wt + OFF_G3IH, g_wt + OFF_G3HH, s_s3, s_x, s_part, s_xg, s_hg);
      glu_mul(g_wt + OFF_GLU3, s_s3, s_o3, s_part);

      // ---- skip: [o1,o2,o3,fw2,pg3*pl2,psub] = 1152
      s_x[tid]        = s_o1[tid];
      s_x[256 + tid]  = s_o2[tid];
      s_x[512 + tid]  = s_o3[tid];
      s_x[768 + tid]  = s_fw2[tid];
      if (tid < 64)       s_x[1024 + tid] = s_pg[3] * s_pl[2 + tid];
      else if (tid < 128) s_x[1024 + tid] = s_psub[tid - 64];
      __syncthreads();
      gemv_part(g_wt + OFF_SKIP, s_x, 1152, 256, s_part);
      __syncthreads();
      s_sk[tid] = tanhf(csum(s_part, 256, tid));
      __syncthreads();
      gemv_part(g_wt + OFF_SKIPGLU, s_sk, 256, 256, s_part);
      __syncthreads();
      s_x[tid] = s_sk[tid] * sigmoidf_(csum(s_part, 256, tid));  // sk2 in s_x[0:256]
      __syncthreads();

      // ---- out = tanh(sk2 @ out_w^T) * gain
      gemv_part(g_wt + OFF_OUT, s_x, 256, 64, s_part);
      __syncthreads();
      if (tid < 64) {
        float v = tanhf(csum(s_part, 64, tid)) * s_gain[0];
        s_out[tid] = v;
        outp[b * 25600 + f * 256 + i * 64 + tid] = v;
      }
      __syncthreads();

      // ---- prev = [prev[64:], out]
      float pv = (tid < 192) ? s_prev[tid + 64] : s_out[tid - 192];
      __syncthreads();
      s_prev[tid] = pv;
      __syncthreads();
    }
  }
}

// ---------------------------------------------------------------------------
extern "C" void kernel_launch(void* const* d_in, const int* in_sizes, int n_in,
                              void* d_out, int out_size) {
  (void)in_sizes; (void)n_in; (void)out_size;
  const float* features = (const float*)d_in[0];
  const float* gfeat    = (const float*)d_in[1];
  const float* prev     = (const float*)d_in[2];
  const int*   periods  = (const int*)d_in[3];
  const float* cond_w1  = (const float*)d_in[4];
  const float* cond_w2  = (const float*)d_in[5];
  const float* cond_w3  = (const float*)d_in[6];
  const float* gain_w   = (const float*)d_in[7];
  const float* gain_b   = (const float*)d_in[8];
  const float* fw_w     = (const float*)d_in[9];
  const float* fw_glu_w = (const float*)d_in[10];
  const float* pg_w     = (const float*)d_in[11];
  const float* pg_b     = (const float*)d_in[12];
  const float* g1ih     = (const float*)d_in[13];
  const float* g1hh     = (const float*)d_in[14];
  const float* g2ih     = (const float*)d_in[15];
  const float* g2hh     = (const float*)d_in[16];
  const float* g3ih     = (const float*)d_in[17];
  const float* g3hh     = (const float*)d_in[18];
  const float* glu1     = (const float*)d_in[19];
  const float* glu2     = (const float*)d_in[20];
  const float* glu3     = (const float*)d_in[21];
  const float* skip_w   = (const float*)d_in[22];
  const float* skipglu  = (const float*)d_in[23];
  const float* out_w    = (const float*)d_in[24];

  float* wt = nullptr;
  cudaGetSymbolAddress((void**)&wt, g_wt);

  auto tp = [&](const float* src, int off, int O, int I) {
    int tot = O * I;
    transpose_k<<<(tot + 255) / 256, 256>>>(src, wt + off, O, I);
  };
  tp(fw_w,     OFF_FW,      256, 520);
  tp(fw_glu_w, OFF_FWGLU,   256, 256);
  tp(g1ih,     OFF_G1IH,    768, 384);
  tp(g1hh,     OFF_G1HH,    768, 256);
  tp(g2ih,     OFF_G2IH,    768, 384);
  tp(g2hh,     OFF_G2HH,    768, 256);
  tp(g3ih,     OFF_G3IH,    768, 384);
  tp(g3hh,     OFF_G3HH,    768, 256);
  tp(glu1,     OFF_GLU1,    256, 256);
  tp(glu2,     OFF_GLU2,    256, 256);
  tp(glu3,     OFF_GLU3,    256, 256);
  tp(skip_w,   OFF_SKIP,    256, 1152);
  tp(skipglu,  OFF_SKIPGLU, 256, 256);
  tp(out_w,    OFF_OUT,     64,  256);
  tp(cond_w1,  OFF_C1,      336, 336);
  tp(cond_w2,  OFF_C2,      336, 336);
  tp(cond_w3,  OFF_C3,      512, 336);

  dim3 cg(NB, NFRAMES);
  cond_kernel<<<cg, 256>>>(features, gfeat);

  main_kernel<<<NB, 256>>>(prev, periods, gain_w, gain_b, pg_w, pg_b, (float*)d_out);
}

// round 2
// speedup vs baseline: 1.2214x; 1.2214x over previous
#include <cuda_runtime.h>
#include <cuda_fp16.h>
#include <math.h>

// ----------------------------------------------------------------------------
// FARGAN vocoder. 64 independent batch rows; 100 frames x 4 subframes of a
// strictly sequential GRU stack. One CTA per batch row runs the recurrence.
// Round 2: main-path weights converted to fp16 (K-major, transposed) -> halves
// L2/L1 weight traffic; GEMV restructured to 8 K-chunks x 32 lanes with up to
// 24 fp32 accumulators/thread for higher MLP. Accumulation stays fp32.
// ----------------------------------------------------------------------------

#define NFRAMES 100
#define NB      64

__device__ __forceinline__ float sigmoidf_(float x) { return 1.0f / (1.0f + expf(-x)); }

// fp16 transposed main-path weights (halves)
enum : int {
  OFFH_FW      = 0,                          // 520 x 256
  OFFH_FWGLU   = OFFH_FW      + 520 * 256,   // 256 x 256
  OFFH_G1IH    = OFFH_FWGLU   + 256 * 256,   // 384 x 768
  OFFH_G1HH    = OFFH_G1IH    + 384 * 768,   // 256 x 768
  OFFH_G2IH    = OFFH_G1HH    + 256 * 768,
  OFFH_G2HH    = OFFH_G2IH    + 384 * 768,
  OFFH_G3IH    = OFFH_G2HH    + 256 * 768,
  OFFH_G3HH    = OFFH_G3IH    + 384 * 768,
  OFFH_GLU1    = OFFH_G3HH    + 256 * 768,
  OFFH_GLU2    = OFFH_GLU1    + 256 * 256,
  OFFH_GLU3    = OFFH_GLU2    + 256 * 256,
  OFFH_SKIP    = OFFH_GLU3    + 256 * 256,   // 1152 x 256
  OFFH_SKIPGLU = OFFH_SKIP    + 1152 * 256,
  OFFH_OUT     = OFFH_SKIPGLU + 256 * 256,   // 256 x 64
  WH_TOTAL     = OFFH_OUT     + 256 * 64
};

// fp32 transposed conditioning weights
enum : int {
  OFFC_C1  = 0,
  OFFC_C2  = OFFC_C1 + 336 * 336,
  OFFC_C3  = OFFC_C2 + 336 * 336,
  WC_TOTAL = OFFC_C3 + 336 * 512
};

__device__ __half g_wh[WH_TOTAL];
__device__ float  g_wc[WC_TOTAL];
__device__ float  g_cond[NFRAMES * NB * 512];

// ---------------------------------------------------------------------------
// transpose fp32: src[O][I] row-major -> dst[I][O]
__global__ void transpose_k(const float* __restrict__ src, float* __restrict__ dst,
                            int O, int I) {
  int idx = blockIdx.x * blockDim.x + threadIdx.x;
  if (idx < O * I) {
    int i = idx / O;
    int o = idx % O;
    dst[idx] = src[o * I + i];
  }
}

// transpose + convert to fp16
__global__ void transpose_h_k(const float* __restrict__ src, __half* __restrict__ dst,
                              int O, int I) {
  int idx = blockIdx.x * blockDim.x + threadIdx.x;
  if (idx < O * I) {
    int i = idx / O;
    int o = idx % O;
    dst[idx] = __float2half(src[o * I + i]);
  }
}

// ---------------------------------------------------------------------------
// fp16 GEMV partial. 256 threads = 8 K-chunks x 32 lanes. Wh is K-major
// [K][N] halves. Each lane owns up to NG groups of 8 consecutive outputs,
// accumulated fp32. part[8][N]; caller syncs, then csum8 combines.
template <int K, int N>
__device__ __forceinline__ void gemv_h(const __half* __restrict__ Wh,
                                       const float* __restrict__ xs,
                                       float* __restrict__ part) {
  const int tid  = threadIdx.x;
  const int kc   = tid >> 5;
  const int lane = tid & 31;
  constexpr int Kc = K / 8;
  constexpr int NV = N / 8;               // float4 groups of 8 halves
  constexpr int NG = (NV + 31) / 32;      // groups per lane

  const float* xk = xs + kc * Kc;
  const float4* __restrict__ W4 =
      reinterpret_cast<const float4*>(Wh) + (size_t)(kc * Kc) * NV;

  float acc[NG][8];
#pragma unroll
  for (int ng = 0; ng < NG; ++ng)
#pragma unroll
    for (int j = 0; j < 8; ++j) acc[ng][j] = 0.f;

#pragma unroll 2
  for (int k = 0; k < Kc; ++k) {
    const float xv = xk[k];
    const float4* wr = W4 + (size_t)k * NV + lane;
#pragma unroll
    for (int ng = 0; ng < NG; ++ng) {
      if (NV >= 32 || lane + ng * 32 < NV) {
        float4 h8 = wr[ng * 32];
        const __half2* hp = reinterpret_cast<const __half2*>(&h8);
#pragma unroll
        for (int j = 0; j < 4; ++j) {
          float2 f = __half22float2(hp[j]);
          acc[ng][2 * j]     = fmaf(xv, f.x, acc[ng][2 * j]);
          acc[ng][2 * j + 1] = fmaf(xv, f.y, acc[ng][2 * j + 1]);
        }
      }
    }
  }

  float4* P4 = reinterpret_cast<float4*>(part + kc * N);
#pragma unroll
  for (int ng = 0; ng < NG; ++ng) {
    if (NV >= 32 || lane + ng * 32 < NV) {
      int g = lane + ng * 32;
      P4[2 * g]     = make_float4(acc[ng][0], acc[ng][1], acc[ng][2], acc[ng][3]);
      P4[2 * g + 1] = make_float4(acc[ng][4], acc[ng][5], acc[ng][6], acc[ng][7]);
    }
  }
}

__device__ __forceinline__ float csum8(const float* part, int N, int j) {
  float a = part[j]         + part[N + j];
  float b = part[2 * N + j] + part[3 * N + j];
  float c = part[4 * N + j] + part[5 * N + j];
  float d = part[6 * N + j] + part[7 * N + j];
  return (a + b) + (c + d);
}

// ---------------------------------------------------------------------------
// fp32 GEMV partial for the conditioning net (4 K-chunks x 64 lanes)
__device__ __forceinline__ void gemv_part(const float* __restrict__ Wt,
                                          const float* __restrict__ xs,
                                          int K, int N, float* part) {
  const int tid = threadIdx.x;
  const int kc  = tid >> 6;
  const int g0  = tid & 63;
  const int Kc  = K >> 2;
  const int G   = N >> 2;
  const float4* __restrict__ W4 = reinterpret_cast<const float4*>(Wt) + (size_t)(kc * Kc) * G;
  const float*  __restrict__ xk = xs + kc * Kc;
  float4* P4 = reinterpret_cast<float4*>(part + kc * N);
  for (int g = g0; g < G; g += 64) {
    float4 acc = make_float4(0.f, 0.f, 0.f, 0.f);
    const float4* wp = W4 + g;
#pragma unroll 4
    for (int k = 0; k < Kc; ++k) {
      const float xv = xk[k];
      const float4 w = wp[(size_t)k * G];
      acc.x = fmaf(xv, w.x, acc.x);
      acc.y = fmaf(xv, w.y, acc.y);
      acc.z = fmaf(xv, w.z, acc.z);
      acc.w = fmaf(xv, w.w, acc.w);
    }
    P4[g] = acc;
  }
}

__device__ __forceinline__ float csum4(const float* part, int N, int j) {
  return (part[j] + part[N + j]) + (part[2 * N + j] + part[3 * N + j]);
}

// ---------------------------------------------------------------------------
// conditioning network for all frames (parallel): grid (64 batch, 100 frames)
__global__ __launch_bounds__(256)
void cond_kernel(const float* __restrict__ feat, const float* __restrict__ gf) {
  __shared__ __align__(16) float s_part[4 * 512];
  __shared__ float s_x[336];
  __shared__ float s_y[336];
  const int b = blockIdx.x, f = blockIdx.y, tid = threadIdx.x;

  for (int j = tid; j < 80; j += 256)  s_x[j]      = feat[(b * 80 + j) * NFRAMES + f];
  for (int j = tid; j < 256; j += 256) s_x[80 + j] = gf[b * 256 + j];
  __syncthreads();
  gemv_part(g_wc + OFFC_C1, s_x, 336, 336, s_part);
  __syncthreads();
  for (int j = tid; j < 336; j += 256) s_y[j] = tanhf(csum4(s_part, 336, j));
  __syncthreads();
  gemv_part(g_wc + OFFC_C2, s_y, 336, 336, s_part);
  __syncthreads();
  for (int j = tid; j < 336; j += 256) s_x[j] = tanhf(csum4(s_part, 336, j));
  __syncthreads();
  gemv_part(g_wc + OFFC_C3, s_x, 336, 512, s_part);
  __syncthreads();
  float* dst = g_cond + (f * NB + b) * 512;
  for (int j = tid; j < 512; j += 256) dst[j] = tanhf(csum4(s_part, 512, j));
}

// ---------------------------------------------------------------------------
// recurrence helpers (all 256 threads call uniformly)
template <int OFF_IH, int OFF_HH>
__device__ __forceinline__ void gru_step(float* s_state, const float* s_xin,
                                         float* s_part, float* s_xg, float* s_hg) {
  const int tid = threadIdx.x;
  gemv_h<384, 768>(g_wh + OFF_IH, s_xin, s_part);
  __syncthreads();
  for (int j = tid; j < 768; j += 256) s_xg[j] = csum8(s_part, 768, j);
  __syncthreads();
  gemv_h<256, 768>(g_wh + OFF_HH, s_state, s_part);
  __syncthreads();
  for (int j = tid; j < 768; j += 256) s_hg[j] = csum8(s_part, 768, j);
  __syncthreads();
  {
    float r = sigmoidf_(s_xg[tid] + s_hg[tid]);
    float z = sigmoidf_(s_xg[256 + tid] + s_hg[256 + tid]);
    float n = tanhf(s_xg[512 + tid] + r * s_hg[512 + tid]);
    s_state[tid] = (1.f - z) * n + z * s_state[tid];
  }
  __syncthreads();
}

template <int OFF_GLU>
__device__ __forceinline__ void glu_mul(const float* src, float* dst, float* s_part) {
  const int tid = threadIdx.x;
  gemv_h<256, 256>(g_wh + OFF_GLU, src, s_part);
  __syncthreads();
  dst[tid] = src[tid] * sigmoidf_(csum8(s_part, 256, tid));
  __syncthreads();
}

// ---------------------------------------------------------------------------
// main sequential kernel: one CTA per batch row
__global__ __launch_bounds__(256)
void main_kernel(const float* __restrict__ prev0,
                 const int*   __restrict__ periods,
                 const float* __restrict__ gain_w,
                 const float* __restrict__ gain_b,
                 const float* __restrict__ pg_w,
                 const float* __restrict__ pg_b,
                 float*       __restrict__ outp) {
  __shared__ __align__(16) float s_part[8 * 768];
  __shared__ float s_x[1152];
  __shared__ float s_xg[768], s_hg[768];
  __shared__ float s_prev[256], s_s1[256], s_s2[256], s_s3[256], s_s4[260];
  __shared__ float s_fw[256], s_fw2[256], s_o1[256], s_o2[256], s_o3[256], s_sk[256];
  __shared__ float s_pl[68], s_psub[64], s_pg[4], s_gain[2], s_out[64];

  const int b = blockIdx.x, tid = threadIdx.x;

  s_prev[tid] = prev0[b * 256 + tid];
  s_s1[tid] = 0.f; s_s2[tid] = 0.f; s_s3[tid] = 0.f;
  s_s4[tid] = 0.f;
  if (tid < 4) s_s4[256 + tid] = 0.f;
  __syncthreads();

  const float gb0 = gain_b[0];

  for (int f = 0; f < NFRAMES; ++f) {
    const int per = periods[b * NFRAMES + f];
    const float* condf = g_cond + (f * NB + b) * 512;

    for (int i = 0; i < 4; ++i) {
      const float* sf = condf + i * 128;

      // ---- gain = exp(sf . gain_w + b) (warp 0)
      if (tid < 32) {
        float d = 0.f;
        for (int k = tid; k < 128; k += 32) d = fmaf(sf[k], gain_w[k], d);
#pragma unroll
        for (int o = 16; o; o >>= 1) d += __shfl_xor_sync(0xffffffffu, d, o);
        if (tid == 0) {
          float g = expf(d + gb0);
          s_gain[0] = g;
          s_gain[1] = 1.0f / (1e-5f + g);
        }
      }
      __syncthreads();
      const float ginv = s_gain[1];

      // ---- pitch-lag gather + scaling; prev_sub
      if (tid < 68) {
        int idx = 256 - per + tid - 2;
        if (idx >= 256) idx -= per;
        s_pl[tid] = s_prev[idx] * ginv;
      } else if (tid >= 128 && tid < 192) {
        s_psub[tid - 128] = s_prev[tid + 64] * ginv;  // prev[192..255]
      }
      __syncthreads();

      // ---- assemble fw input: [sf(128), psub(64), pl(68), s4(260)] = 520
      if (tid < 128)       s_x[tid] = sf[tid];
      else if (tid < 192)  s_x[tid] = s_psub[tid - 128];
      else                 s_x[tid] = s_pl[tid - 192];
      if (tid < 4)         s_x[256 + tid] = s_pl[64 + tid];
      s_x[260 + tid] = s_s4[tid];
      if (tid < 4) s_x[516 + tid] = s_s4[256 + tid];
      __syncthreads();

      // s4 <- sif (copy of x[0:260]); runs alongside fw gemv (both read s_x)
      s_s4[tid] = s_x[tid];
      if (tid < 4) s_s4[256 + tid] = s_x[256 + tid];

      gemv_h<520, 256>(g_wh + OFFH_FW, s_x, s_part);
      __syncthreads();
      s_fw[tid] = tanhf(csum8(s_part, 256, tid));
      __syncthreads();

      gemv_h<256, 256>(g_wh + OFFH_FWGLU, s_fw, s_part);
      __syncthreads();
      s_fw2[tid] = s_fw[tid] * sigmoidf_(csum8(s_part, 256, tid));
      __syncthreads();

      // ---- pg (4 warps)
      if (tid < 128) {
        int w = tid >> 5, l = tid & 31;
        float d = 0.f;
        for (int k = l; k < 256; k += 32) d = fmaf(s_fw2[k], pg_w[w * 256 + k], d);
#pragma unroll
        for (int o = 16; o; o >>= 1) d += __shfl_xor_sync(0xffffffffu, d, o);
        if (l == 0) s_pg[w] = sigmoidf_(d + pg_b[w]) + 1e-5f;
      }
      __syncthreads();

      // ---- GRU1
      s_x[tid] = s_fw2[tid];
      if (tid < 64)       s_x[256 + tid] = s_pg[0] * s_pl[2 + tid];
      else if (tid < 128) s_x[256 + tid] = s_psub[tid - 64];
      __syncthreads();
      gru_step<OFFH_G1IH, OFFH_G1HH>(s_s1, s_x, s_part, s_xg, s_hg);
      glu_mul<OFFH_GLU1>(s_s1, s_o1, s_part);

      // ---- GRU2
      s_x[tid] = s_o1[tid];
      if (tid < 64)       s_x[256 + tid] = s_pg[1] * s_pl[2 + tid];
      else if (tid < 128) s_x[256 + tid] = s_psub[tid - 64];
      __syncthreads();
      gru_step<OFFH_G2IH, OFFH_G2HH>(s_s2, s_x, s_part, s_xg, s_hg);
      glu_mul<OFFH_GLU2>(s_s2, s_o2, s_part);

      // ---- GRU3
      s_x[tid] = s_o2[tid];
      if (tid < 64)       s_x[256 + tid] = s_pg[2] * s_pl[2 + tid];
      else if (tid < 128) s_x[256 + tid] = s_psub[tid - 64];
      __syncthreads();
      gru_step<OFFH_G3IH, OFFH_G3HH>(s_s3, s_x, s_part, s_xg, s_hg);
      glu_mul<OFFH_GLU3>(s_s3, s_o3, s_part);

      // ---- skip: [o1,o2,o3,fw2,pg3*pl2,psub] = 1152
      s_x[tid]        = s_o1[tid];
      s_x[256 + tid]  = s_o2[tid];
      s_x[512 + tid]  = s_o3[tid];
      s_x[768 + tid]  = s_fw2[tid];
      if (tid < 64)       s_x[1024 + tid] = s_pg[3] * s_pl[2 + tid];
      else if (tid < 128) s_x[1024 + tid] = s_psub[tid - 64];
      __syncthreads();
      gemv_h<1152, 256>(g_wh + OFFH_SKIP, s_x, s_part);
      __syncthreads();
      s_sk[tid] = tanhf(csum8(s_part, 256, tid));
      __syncthreads();
      gemv_h<256, 256>(g_wh + OFFH_SKIPGLU, s_sk, s_part);
      __syncthreads();
      s_x[tid] = s_sk[tid] * sigmoidf_(csum8(s_part, 256, tid));  // sk2 in s_x[0:256]
      __syncthreads();

      // ---- out = tanh(sk2 @ out_w^T) * gain
      gemv_h<256, 64>(g_wh + OFFH_OUT, s_x, s_part);
      __syncthreads();
      if (tid < 64) {
        float v = tanhf(csum8(s_part, 64, tid)) * s_gain[0];
        s_out[tid] = v;
        outp[b * 25600 + f * 256 + i * 64 + tid] = v;
      }
      __syncthreads();

      // ---- prev = [prev[64:], out]
      float pv = (tid < 192) ? s_prev[tid + 64] : s_out[tid - 192];
      __syncthreads();
      s_prev[tid] = pv;
      __syncthreads();
    }
  }
}

// ---------------------------------------------------------------------------
extern "C" void kernel_launch(void* const* d_in, const int* in_sizes, int n_in,
                              void* d_out, int out_size) {
  (void)in_sizes; (void)n_in; (void)out_size;
  const float* features = (const float*)d_in[0];
  const float* gfeat    = (const float*)d_in[1];
  const float* prev     = (const float*)d_in[2];
  const int*   periods  = (const int*)d_in[3];
  const float* cond_w1  = (const float*)d_in[4];
  const float* cond_w2  = (const float*)d_in[5];
  const float* cond_w3  = (const float*)d_in[6];
  const float* gain_w   = (const float*)d_in[7];
  const float* gain_b   = (const float*)d_in[8];
  const float* fw_w     = (const float*)d_in[9];
  const float* fw_glu_w = (const float*)d_in[10];
  const float* pg_w     = (const float*)d_in[11];
  const float* pg_b     = (const float*)d_in[12];
  const float* g1ih     = (const float*)d_in[13];
  const float* g1hh     = (const float*)d_in[14];
  const float* g2ih     = (const float*)d_in[15];
  const float* g2hh     = (const float*)d_in[16];
  const float* g3ih     = (const float*)d_in[17];
  const float* g3hh     = (const float*)d_in[18];
  const float* glu1     = (const float*)d_in[19];
  const float* glu2     = (const float*)d_in[20];
  const float* glu3     = (const float*)d_in[21];
  const float* skip_w   = (const float*)d_in[22];
  const float* skipglu  = (const float*)d_in[23];
  const float* out_w    = (const float*)d_in[24];

  __half* wh = nullptr;
  float*  wc = nullptr;
  cudaGetSymbolAddress((void**)&wh, g_wh);
  cudaGetSymbolAddress((void**)&wc, g_wc);

  auto tph = [&](const float* src, int off, int O, int I) {
    int tot = O * I;
    transpose_h_k<<<(tot + 255) / 256, 256>>>(src, wh + off, O, I);
  };
  auto tpc = [&](const float* src, int off, int O, int I) {
    int tot = O * I;
    transpose_k<<<(tot + 255) / 256, 256>>>(src, wc + off, O, I);
  };

  tph(fw_w,     OFFH_FW,      256, 520);
  tph(fw_glu_w, OFFH_FWGLU,   256, 256);
  tph(g1ih,     OFFH_G1IH,    768, 384);
  tph(g1hh,     OFFH_G1HH,    768, 256);
  tph(g2ih,     OFFH_G2IH,    768, 384);
  tph(g2hh,     OFFH_G2HH,    768, 256);
  tph(g3ih,     OFFH_G3IH,    768, 384);
  tph(g3hh,     OFFH_G3HH,    768, 256);
  tph(glu1,     OFFH_GLU1,    256, 256);
  tph(glu2,     OFFH_GLU2,    256, 256);
  tph(glu3,     OFFH_GLU3,    256, 256);
  tph(skip_w,   OFFH_SKIP,    256, 1152);
  tph(skipglu,  OFFH_SKIPGLU, 256, 256);
  tph(out_w,    OFFH_OUT,     64,  256);
  tpc(cond_w1,  OFFC_C1,      336, 336);
  tpc(cond_w2,  OFFC_C2,      336, 336);
  tpc(cond_w3,  OFFC_C3,      512, 336);

  dim3 cg(NB, NFRAMES);
  cond_kernel<<<cg, 256>>>(features, gfeat);

  main_kernel<<<NB, 256>>>(prev, periods, gain_w, gain_b, pg_w, pg_b, (float*)d_out);
}

// round 3
// speedup vs baseline: 1.2233x; 1.0016x over previous
#include <cuda_runtime.h>
#include <cuda_fp16.h>
#include <math.h>

// ----------------------------------------------------------------------------
// FARGAN vocoder. 64 independent batch rows; 100 frames x 4 subframes of a
// strictly sequential GRU stack. One CTA per batch row runs the recurrence.
// Round 2: main-path weights converted to fp16 (K-major, transposed) -> halves
// L2/L1 weight traffic; GEMV restructured to 8 K-chunks x 32 lanes with up to
// 24 fp32 accumulators/thread for higher MLP. Accumulation stays fp32.
// ----------------------------------------------------------------------------

#define NFRAMES 100
#define NB      64

__device__ __forceinline__ float sigmoidf_(float x) { return 1.0f / (1.0f + expf(-x)); }

// fp16 transposed main-path weights (halves)
enum : int {
  OFFH_FW      = 0,                          // 520 x 256
  OFFH_FWGLU   = OFFH_FW      + 520 * 256,   // 256 x 256
  OFFH_G1IH    = OFFH_FWGLU   + 256 * 256,   // 384 x 768
  OFFH_G1HH    = OFFH_G1IH    + 384 * 768,   // 256 x 768
  OFFH_G2IH    = OFFH_G1HH    + 256 * 768,
  OFFH_G2HH    = OFFH_G2IH    + 384 * 768,
  OFFH_G3IH    = OFFH_G2HH    + 256 * 768,
  OFFH_G3HH    = OFFH_G3IH    + 384 * 768,
  OFFH_GLU1    = OFFH_G3HH    + 256 * 768,
  OFFH_GLU2    = OFFH_GLU1    + 256 * 256,
  OFFH_GLU3    = OFFH_GLU2    + 256 * 256,
  OFFH_SKIP    = OFFH_GLU3    + 256 * 256,   // 1152 x 256
  OFFH_SKIPGLU = OFFH_SKIP    + 1152 * 256,
  OFFH_OUT     = OFFH_SKIPGLU + 256 * 256,   // 256 x 64
  WH_TOTAL     = OFFH_OUT     + 256 * 64
};

// fp32 transposed conditioning weights
enum : int {
  OFFC_C1  = 0,
  OFFC_C2  = OFFC_C1 + 336 * 336,
  OFFC_C3  = OFFC_C2 + 336 * 336,
  WC_TOTAL = OFFC_C3 + 336 * 512
};

__device__ __half g_wh[WH_TOTAL];
__device__ float  g_wc[WC_TOTAL];
__device__ float  g_cond[NFRAMES * NB * 512];

// ---------------------------------------------------------------------------
// transpose fp32: src[O][I] row-major -> dst[I][O]
__global__ void transpose_k(const float* __restrict__ src, float* __restrict__ dst,
                            int O, int I) {
  int idx = blockIdx.x * blockDim.x + threadIdx.x;
  if (idx < O * I) {
    int i = idx / O;
    int o = idx % O;
    dst[idx] = src[o * I + i];
  }
}

// transpose + convert to fp16
__global__ void transpose_h_k(const float* __restrict__ src, __half* __restrict__ dst,
                              int O, int I) {
  int idx = blockIdx.x * blockDim.x + threadIdx.x;
  if (idx < O * I) {
    int i = idx / O;
    int o = idx % O;
    dst[idx] = __float2half(src[o * I + i]);
  }
}

// ---------------------------------------------------------------------------
// fp16 GEMV partial. 256 threads = 8 K-chunks x 32 lanes. Wh is K-major
// [K][N] halves. Each lane owns up to NG groups of 8 consecutive outputs,
// accumulated fp32. part[8][N]; caller syncs, then csum8 combines.
template <int K, int N>
__device__ __forceinline__ void gemv_h(const __half* __restrict__ Wh,
                                       const float* __restrict__ xs,
                                       float* __restrict__ part) {
  const int tid  = threadIdx.x;
  const int kc   = tid >> 5;
  const int lane = tid & 31;
  constexpr int Kc = K / 8;
  constexpr int NV = N / 8;               // float4 groups of 8 halves
  constexpr int NG = (NV + 31) / 32;      // groups per lane

  const float* xk = xs + kc * Kc;
  const float4* __restrict__ W4 =
      reinterpret_cast<const float4*>(Wh) + (size_t)(kc * Kc) * NV;

  float acc[NG][8];
#pragma unroll
  for (int ng = 0; ng < NG; ++ng)
#pragma unroll
    for (int j = 0; j < 8; ++j) acc[ng][j] = 0.f;

#pragma unroll 2
  for (int k = 0; k < Kc; ++k) {
    const float xv = xk[k];
    const float4* wr = W4 + (size_t)k * NV + lane;
#pragma unroll
    for (int ng = 0; ng < NG; ++ng) {
      if (NV >= 32 || lane + ng * 32 < NV) {
        float4 h8 = wr[ng * 32];
        const __half2* hp = reinterpret_cast<const __half2*>(&h8);
#pragma unroll
        for (int j = 0; j < 4; ++j) {
          float2 f = __half22float2(hp[j]);
          acc[ng][2 * j]     = fmaf(xv, f.x, acc[ng][2 * j]);
          acc[ng][2 * j + 1] = fmaf(xv, f.y, acc[ng][2 * j + 1]);
        }
      }
    }
  }

  float4* P4 = reinterpret_cast<float4*>(part + kc * N);
#pragma unroll
  for (int ng = 0; ng < NG; ++ng) {
    if (NV >= 32 || lane + ng * 32 < NV) {
      int g = lane + ng * 32;
      P4[2 * g]     = make_float4(acc[ng][0], acc[ng][1], acc[ng][2], acc[ng][3]);
      P4[2 * g + 1] = make_float4(acc[ng][4], acc[ng][5], acc[ng][6], acc[ng][7]);
    }
  }
}

__device__ __forceinline__ float csum8(const float* part, int N, int j) {
  float a = part[j]         + part[N + j];
  float b = part[2 * N + j] + part[3 * N + j];
  float c = part[4 * N + j] + part[5 * N + j];
  float d = part[6 * N + j] + part[7 * N + j];
  return (a + b) + (c + d);
}

// ---------------------------------------------------------------------------
// fp32 GEMV partial for the conditioning net (4 K-chunks x 64 lanes)
__device__ __forceinline__ void gemv_part(const float* __restrict__ Wt,
                                          const float* __restrict__ xs,
                                          int K, int N, float* part) {
  const int tid = threadIdx.x;
  const int kc  = tid >> 6;
  const int g0  = tid & 63;
  const int Kc  = K >> 2;
  const int G   = N >> 2;
  const float4* __restrict__ W4 = reinterpret_cast<const float4*>(Wt) + (size_t)(kc * Kc) * G;
  const float*  __restrict__ xk = xs + kc * Kc;
  float4* P4 = reinterpret_cast<float4*>(part + kc * N);
  for (int g = g0; g < G; g += 64) {
    float4 acc = make_float4(0.f, 0.f, 0.f, 0.f);
    const float4* wp = W4 + g;
#pragma unroll 4
    for (int k = 0; k < Kc; ++k) {
      const float xv = xk[k];
      const float4 w = wp[(size_t)k * G];
      acc.x = fmaf(xv, w.x, acc.x);
      acc.y = fmaf(xv, w.y, acc.y);
      acc.z = fmaf(xv, w.z, acc.z);
      acc.w = fmaf(xv, w.w, acc.w);
    }
    P4[g] = acc;
  }
}

__device__ __forceinline__ float csum4(const float* part, int N, int j) {
  return (part[j] + part[N + j]) + (part[2 * N + j] + part[3 * N + j]);
}

// ---------------------------------------------------------------------------
// conditioning network for all frames (parallel): grid (64 batch, 100 frames)
__global__ __launch_bounds__(256)
void cond_kernel(const float* __restrict__ feat, const float* __restrict__ gf) {
  __shared__ __align__(16) float s_part[4 * 512];
  __shared__ float s_x[336];
  __shared__ float s_y[336];
  const int b = blockIdx.x, f = blockIdx.y, tid = threadIdx.x;

  for (int j = tid; j < 80; j += 256)  s_x[j]      = feat[(b * 80 + j) * NFRAMES + f];
  for (int j = tid; j < 256; j += 256) s_x[80 + j] = gf[b * 256 + j];
  __syncthreads();
  gemv_part(g_wc + OFFC_C1, s_x, 336, 336, s_part);
  __syncthreads();
  for (int j = tid; j < 336; j += 256) s_y[j] = tanhf(csum4(s_part, 336, j));
  __syncthreads();
  gemv_part(g_wc + OFFC_C2, s_y, 336, 336, s_part);
  __syncthreads();
  for (int j = tid; j < 336; j += 256) s_x[j] = tanhf(csum4(s_part, 336, j));
  __syncthreads();
  gemv_part(g_wc + OFFC_C3, s_x, 336, 512, s_part);
  __syncthreads();
  float* dst = g_cond + (f * NB + b) * 512;
  for (int j = tid; j < 512; j += 256) dst[j] = tanhf(csum4(s_part, 512, j));
}

// ---------------------------------------------------------------------------
// recurrence helpers (all 256 threads call uniformly)
template <int OFF_IH, int OFF_HH>
__device__ __forceinline__ void gru_step(float* s_state, const float* s_xin,
                                         float* s_part, float* s_xg, float* s_hg) {
  const int tid = threadIdx.x;
  gemv_h<384, 768>(g_wh + OFF_IH, s_xin, s_part);
  __syncthreads();
  for (int j = tid; j < 768; j += 256) s_xg[j] = csum8(s_part, 768, j);
  __syncthreads();
  gemv_h<256, 768>(g_wh + OFF_HH, s_state, s_part);
  __syncthreads();
  for (int j = tid; j < 768; j += 256) s_hg[j] = csum8(s_part, 768, j);
  __syncthreads();
  {
    float r = sigmoidf_(s_xg[tid] + s_hg[tid]);
    float z = sigmoidf_(s_xg[256 + tid] + s_hg[256 + tid]);
    float n = tanhf(s_xg[512 + tid] + r * s_hg[512 + tid]);
    s_state[tid] = (1.f - z) * n + z * s_state[tid];
  }
  __syncthreads();
}

template <int OFF_GLU>
__device__ __forceinline__ void glu_mul(const float* src, float* dst, float* s_part) {
  const int tid = threadIdx.x;
  gemv_h<256, 256>(g_wh + OFF_GLU, src, s_part);
  __syncthreads();
  dst[tid] = src[tid] * sigmoidf_(csum8(s_part, 256, tid));
  __syncthreads();
}

// ---------------------------------------------------------------------------
// main sequential kernel: one CTA per batch row
__global__ __launch_bounds__(256)
void main_kernel(const float* __restrict__ prev0,
                 const int*   __restrict__ periods,
                 const float* __restrict__ gain_w,
                 const float* __restrict__ gain_b,
                 const float* __restrict__ pg_w,
                 const float* __restrict__ pg_b,
                 float*       __restrict__ outp) {
  __shared__ __align__(16) float s_part[8 * 768];
  __shared__ float s_x[1152];
  __shared__ float s_xg[768], s_hg[768];
  __shared__ float s_prev[256], s_s1[256], s_s2[256], s_s3[256], s_s4[260];
  __shared__ float s_fw[256], s_fw2[256], s_o1[256], s_o2[256], s_o3[256], s_sk[256];
  __shared__ float s_pl[68], s_psub[64], s_pg[4], s_gain[2], s_out[64];

  const int b = blockIdx.x, tid = threadIdx.x;

  s_prev[tid] = prev0[b * 256 + tid];
  s_s1[tid] = 0.f; s_s2[tid] = 0.f; s_s3[tid] = 0.f;
  s_s4[tid] = 0.f;
  if (tid < 4) s_s4[256 + tid] = 0.f;
  __syncthreads();

  const float gb0 = gain_b[0];

  for (int f = 0; f < NFRAMES; ++f) {
    const int per = periods[b * NFRAMES + f];
    const float* condf = g_cond + (f * NB + b) * 512;

    for (int i = 0; i < 4; ++i) {
      const float* sf = condf + i * 128;

      // ---- gain = exp(sf . gain_w + b) (warp 0)
      if (tid < 32) {
        float d = 0.f;
        for (int k = tid; k < 128; k += 32) d = fmaf(sf[k], gain_w[k], d);
#pragma unroll
        for (int o = 16; o; o >>= 1) d += __shfl_xor_sync(0xffffffffu, d, o);
        if (tid == 0) {
          float g = expf(d + gb0);
          s_gain[0] = g;
          s_gain[1] = 1.0f / (1e-5f + g);
        }
      }
      __syncthreads();
      const float ginv = s_gain[1];

      // ---- pitch-lag gather + scaling; prev_sub
      if (tid < 68) {
        int idx = 256 - per + tid - 2;
        if (idx >= 256) idx -= per;
        s_pl[tid] = s_prev[idx] * ginv;
      } else if (tid >= 128 && tid < 192) {
        s_psub[tid - 128] = s_prev[tid + 64] * ginv;  // prev[192..255]
      }
      __syncthreads();

      // ---- assemble fw input: [sf(128), psub(64), pl(68), s4(260)] = 520
      if (tid < 128)       s_x[tid] = sf[tid];
      else if (tid < 192)  s_x[tid] = s_psub[tid - 128];
      else                 s_x[tid] = s_pl[tid - 192];
      if (tid < 4)         s_x[256 + tid] = s_pl[64 + tid];
      s_x[260 + tid] = s_s4[tid];
      if (tid < 4) s_x[516 + tid] = s_s4[256 + tid];
      __syncthreads();

      // s4 <- sif (copy of x[0:260]); runs alongside fw gemv (both read s_x)
      s_s4[tid] = s_x[tid];
      if (tid < 4) s_s4[256 + tid] = s_x[256 + tid];

      gemv_h<520, 256>(g_wh + OFFH_FW, s_x, s_part);
      __syncthreads();
      s_fw[tid] = tanhf(csum8(s_part, 256, tid));
      __syncthreads();

      gemv_h<256, 256>(g_wh + OFFH_FWGLU, s_fw, s_part);
      __syncthreads();
      s_fw2[tid] = s_fw[tid] * sigmoidf_(csum8(s_part, 256, tid));
      __syncthreads();

      // ---- pg (4 warps)
      if (tid < 128) {
        int w = tid >> 5, l = tid & 31;
        float d = 0.f;
        for (int k = l; k < 256; k += 32) d = fmaf(s_fw2[k], pg_w[w * 256 + k], d);
#pragma unroll
        for (int o = 16; o; o >>= 1) d += __shfl_xor_sync(0xffffffffu, d, o);
        if (l == 0) s_pg[w] = sigmoidf_(d + pg_b[w]) + 1e-5f;
      }
      __syncthreads();

      // ---- GRU1
      s_x[tid] = s_fw2[tid];
      if (tid < 64)       s_x[256 + tid] = s_pg[0] * s_pl[2 + tid];
      else if (tid < 128) s_x[256 + tid] = s_psub[tid - 64];
      __syncthreads();
      gru_step<OFFH_G1IH, OFFH_G1HH>(s_s1, s_x, s_part, s_xg, s_hg);
      glu_mul<OFFH_GLU1>(s_s1, s_o1, s_part);

      // ---- GRU2
      s_x[tid] = s_o1[tid];
      if (tid < 64)       s_x[256 + tid] = s_pg[1] * s_pl[2 + tid];
      else if (tid < 128) s_x[256 + tid] = s_psub[tid - 64];
      __syncthreads();
      gru_step<OFFH_G2IH, OFFH_G2HH>(s_s2, s_x, s_part, s_xg, s_hg);
      glu_mul<OFFH_GLU2>(s_s2, s_o2, s_part);

      // ---- GRU3
      s_x[tid] = s_o2[tid];
      if (tid < 64)       s_x[256 + tid] = s_pg[2] * s_pl[2 + tid];
      else if (tid < 128) s_x[256 + tid] = s_psub[tid - 64];
      __syncthreads();
      gru_step<OFFH_G3IH, OFFH_G3HH>(s_s3, s_x, s_part, s_xg, s_hg);
      glu_mul<OFFH_GLU3>(s_s3, s_o3, s_part);

      // ---- skip: [o1,o2,o3,fw2,pg3*pl2,psub] = 1152
      s_x[tid]        = s_o1[tid];
      s_x[256 + tid]  = s_o2[tid];
      s_x[512 + tid]  = s_o3[tid];
      s_x[768 + tid]  = s_fw2[tid];
      if (tid < 64)       s_x[1024 + tid] = s_pg[3] * s_pl[2 + tid];
      else if (tid < 128) s_x[1024 + tid] = s_psub[tid - 64];
      __syncthreads();
      gemv_h<1152, 256>(g_wh + OFFH_SKIP, s_x, s_part);
      __syncthreads();
      s_sk[tid] = tanhf(csum8(s_part, 256, tid));
      __syncthreads();
      gemv_h<256, 256>(g_wh + OFFH_SKIPGLU, s_sk, s_part);
      __syncthreads();
      s_x[tid] = s_sk[tid] * sigmoidf_(csum8(s_part, 256, tid));  // sk2 in s_x[0:256]
      __syncthreads();

      // ---- out = tanh(sk2 @ out_w^T) * gain
      gemv_h<256, 64>(g_wh + OFFH_OUT, s_x, s_part);
      __syncthreads();
      if (tid < 64) {
        float v = tanhf(csum8(s_part, 64, tid)) * s_gain[0];
        s_out[tid] = v;
        outp[b * 25600 + f * 256 + i * 64 + tid] = v;
      }
      __syncthreads();

      // ---- prev = [prev[64:], out]
      float pv = (tid < 192) ? s_prev[tid + 64] : s_out[tid - 192];
      __syncthreads();
      s_prev[tid] = pv;
      __syncthreads();
    }
  }
}

// ---------------------------------------------------------------------------
extern "C" void kernel_launch(void* const* d_in, const int* in_sizes, int n_in,
                              void* d_out, int out_size) {
  (void)in_sizes; (void)n_in; (void)out_size;
  const float* features = (const float*)d_in[0];
  const float* gfeat    = (const float*)d_in[1];
  const float* prev     = (const float*)d_in[2];
  const int*   periods  = (const int*)d_in[3];
  const float* cond_w1  = (const float*)d_in[4];
  const float* cond_w2  = (const float*)d_in[5];
  const float* cond_w3  = (const float*)d_in[6];
  const float* gain_w   = (const float*)d_in[7];
  const float* gain_b   = (const float*)d_in[8];
  const float* fw_w     = (const float*)d_in[9];
  const float* fw_glu_w = (const float*)d_in[10];
  const float* pg_w     = (const float*)d_in[11];
  const float* pg_b     = (const float*)d_in[12];
  const float* g1ih     = (const float*)d_in[13];
  const float* g1hh     = (const float*)d_in[14];
  const float* g2ih     = (const float*)d_in[15];
  const float* g2hh     = (const float*)d_in[16];
  const float* g3ih     = (const float*)d_in[17];
  const float* g3hh     = (const float*)d_in[18];
  const float* glu1     = (const float*)d_in[19];
  const float* glu2     = (const float*)d_in[20];
  const float* glu3     = (const float*)d_in[21];
  const float* skip_w   = (const float*)d_in[22];
  const float* skipglu  = (const float*)d_in[23];
  const float* out_w    = (const float*)d_in[24];

  __half* wh = nullptr;
  float*  wc = nullptr;
  cudaGetSymbolAddress((void**)&wh, g_wh);
  cudaGetSymbolAddress((void**)&wc, g_wc);

  auto tph = [&](const float* src, int off, int O, int I) {
    int tot = O * I;
    transpose_h_k<<<(tot + 255) / 256, 256>>>(src, wh + off, O, I);
  };
  auto tpc = [&](const float* src, int off, int O, int I) {
    int tot = O * I;
    transpose_k<<<(tot + 255) / 256, 256>>>(src, wc + off, O, I);
  };

  tph(fw_w,     OFFH_FW,      256, 520);
  tph(fw_glu_w, OFFH_FWGLU,   256, 256);
  tph(g1ih,     OFFH_G1IH,    768, 384);
  tph(g1hh,     OFFH_G1HH,    768, 256);
  tph(g2ih,     OFFH_G2IH,    768, 384);
  tph(g2hh,     OFFH_G2HH,    768, 256);
  tph(g3ih,     OFFH_G3IH,    768, 384);
  tph(g3hh,     OFFH_G3HH,    768, 256);
  tph(glu1,     OFFH_GLU1,    256, 256);
  tph(glu2,     OFFH_GLU2,    256, 256);
  tph(glu3,     OFFH_GLU3,    256, 256);
  tph(skip_w,   OFFH_SKIP,    256, 1152);
  tph(skipglu,  OFFH_SKIPGLU, 256, 256);
  tph(out_w,    OFFH_OUT,     64,  256);
  tpc(cond_w1,  OFFC_C1,      336, 336);
  tpc(cond_w2,  OFFC_C2,      336, 336);
  tpc(cond_w3,  OFFC_C3,      512, 336);

  dim3 cg(NB, NFRAMES);
  cond_kernel<<<cg, 256>>>(features, gfeat);

  main_kernel<<<NB, 256>>>(prev, periods, gain_w, gain_b, pg_w, pg_b, (float*)d_out);
}

// round 4
// speedup vs baseline: 2.3727x; 1.9395x over previous
#include <cuda_runtime.h>
#include <cuda_fp16.h>
#include <math.h>

// ----------------------------------------------------------------------------
// FARGAN vocoder. 64 independent batch rows; 100 frames x 4 subframes of a
// strictly sequential GRU stack. One CTA per batch row runs the recurrence.
// Round 3: 1024 threads/CTA (32 warps). GEMV = 32 K-chunks x 32 lanes with
// fp32 partials in dynamic SMEM (96KB). 4x fewer loads per thread + 4x more
// warps issuing -> covers L2 latency (round-2 bottleneck). fp16 weights.
// ----------------------------------------------------------------------------

#define NFRAMES 100
#define NB      64
#define NTHREADS 1024

__device__ __forceinline__ float sigmoidf_(float x) { return 1.0f / (1.0f + expf(-x)); }

// fp16 transposed main-path weights (K padded to /32)
enum : int {
  OFFH_FW      = 0,                          // 544 x 256 (520 padded)
  OFFH_FWGLU   = OFFH_FW      + 544 * 256,   // 256 x 256
  OFFH_G1IH    = OFFH_FWGLU   + 256 * 256,   // 384 x 768
  OFFH_G1HH    = OFFH_G1IH    + 384 * 768,   // 256 x 768
  OFFH_G2IH    = OFFH_G1HH    + 256 * 768,
  OFFH_G2HH    = OFFH_G2IH    + 384 * 768,
  OFFH_G3IH    = OFFH_G2HH    + 256 * 768,
  OFFH_G3HH    = OFFH_G3IH    + 384 * 768,
  OFFH_GLU1    = OFFH_G3HH    + 256 * 768,
  OFFH_GLU2    = OFFH_GLU1    + 256 * 256,
  OFFH_GLU3    = OFFH_GLU2    + 256 * 256,
  OFFH_SKIP    = OFFH_GLU3    + 256 * 256,   // 1152 x 256
  OFFH_SKIPGLU = OFFH_SKIP    + 1152 * 256,
  OFFH_OUT     = OFFH_SKIPGLU + 256 * 256,   // 256 x 64
  WH_TOTAL     = OFFH_OUT     + 256 * 64
};

// fp32 transposed conditioning weights
enum : int {
  OFFC_C1  = 0,
  OFFC_C2  = OFFC_C1 + 336 * 336,
  OFFC_C3  = OFFC_C2 + 336 * 336,
  WC_TOTAL = OFFC_C3 + 336 * 512
};

__device__ __half g_wh[WH_TOTAL];
__device__ float  g_wc[WC_TOTAL];
__device__ float  g_cond[NFRAMES * NB * 512];

// ---------------------------------------------------------------------------
// transpose fp32: src[O][I] row-major -> dst[I][O]
__global__ void transpose_k(const float* __restrict__ src, float* __restrict__ dst,
                            int O, int I) {
  int idx = blockIdx.x * blockDim.x + threadIdx.x;
  if (idx < O * I) {
    int i = idx / O;
    int o = idx % O;
    dst[idx] = src[o * I + i];
  }
}

// transpose + convert to fp16, with K padding (rows i >= I become zero)
__global__ void transpose_h_k(const float* __restrict__ src, __half* __restrict__ dst,
                              int O, int I, int Ipad) {
  int idx = blockIdx.x * blockDim.x + threadIdx.x;
  if (idx < O * Ipad) {
    int i = idx / O;
    int o = idx % O;
    dst[idx] = (i < I) ? __float2half(src[o * I + i]) : __float2half(0.0f);
  }
}

// ---------------------------------------------------------------------------
// fp16 GEMV partial, 1024 threads = 32 K-chunks x 32 lanes. Wh is K-major
// [K][N] halves (K % 32 == 0, N % 8 == 0). Each lane owns NG groups of 8
// consecutive outputs; fp32 accumulate. part[32][N]; caller syncs + csum32.
template <int K, int N>
__device__ __forceinline__ void gemv32(const __half* __restrict__ Wh,
                                       const float* __restrict__ xs,
                                       float* __restrict__ part) {
  const int tid  = threadIdx.x;
  const int kc   = tid >> 5;
  const int lane = tid & 31;
  constexpr int Kc = K / 32;
  constexpr int NV = N / 8;               // float4 groups of 8 halves
  constexpr int NG = (NV + 31) / 32;      // groups per lane

  const float* xk = xs + kc * Kc;
  const float4* __restrict__ W4 =
      reinterpret_cast<const float4*>(Wh) + (size_t)(kc * Kc) * NV;

  float acc[NG][8];
#pragma unroll
  for (int ng = 0; ng < NG; ++ng)
#pragma unroll
    for (int j = 0; j < 8; ++j) acc[ng][j] = 0.f;

#pragma unroll 4
  for (int k = 0; k < Kc; ++k) {
    const float xv = xk[k];
    const float4* wr = W4 + (size_t)k * NV + lane;
#pragma unroll
    for (int ng = 0; ng < NG; ++ng) {
      if (NV >= 32 || lane + ng * 32 < NV) {
        float4 h8 = wr[ng * 32];
        const __half2* hp = reinterpret_cast<const __half2*>(&h8);
#pragma unroll
        for (int j = 0; j < 4; ++j) {
          float2 f = __half22float2(hp[j]);
          acc[ng][2 * j]     = fmaf(xv, f.x, acc[ng][2 * j]);
          acc[ng][2 * j + 1] = fmaf(xv, f.y, acc[ng][2 * j + 1]);
        }
      }
    }
  }

  float4* P4 = reinterpret_cast<float4*>(part + kc * N);
#pragma unroll
  for (int ng = 0; ng < NG; ++ng) {
    if (NV >= 32 || lane + ng * 32 < NV) {
      int g = lane + ng * 32;
      P4[2 * g]     = make_float4(acc[ng][0], acc[ng][1], acc[ng][2], acc[ng][3]);
      P4[2 * g + 1] = make_float4(acc[ng][4], acc[ng][5], acc[ng][6], acc[ng][7]);
    }
  }
}

__device__ __forceinline__ float csum32(const float* __restrict__ part, int N, int j) {
  float s = 0.f;
#pragma unroll
  for (int c = 0; c < 32; c += 4) {
    float a = part[c * N + j]       + part[(c + 1) * N + j];
    float b = part[(c + 2) * N + j] + part[(c + 3) * N + j];
    s += (a + b);
  }
  return s;
}

// ---------------------------------------------------------------------------
// fp32 GEMV partial for the conditioning net (4 K-chunks x 64 lanes, 256 thr)
__device__ __forceinline__ void gemv_part(const float* __restrict__ Wt,
                                          const float* __restrict__ xs,
                                          int K, int N, float* part) {
  const int tid = threadIdx.x;
  const int kc  = tid >> 6;
  const int g0  = tid & 63;
  const int Kc  = K >> 2;
  const int G   = N >> 2;
  const float4* __restrict__ W4 = reinterpret_cast<const float4*>(Wt) + (size_t)(kc * Kc) * G;
  const float*  __restrict__ xk = xs + kc * Kc;
  float4* P4 = reinterpret_cast<float4*>(part + kc * N);
  for (int g = g0; g < G; g += 64) {
    float4 acc = make_float4(0.f, 0.f, 0.f, 0.f);
    const float4* wp = W4 + g;
#pragma unroll 4
    for (int k = 0; k < Kc; ++k) {
      const float xv = xk[k];
      const float4 w = wp[(size_t)k * G];
      acc.x = fmaf(xv, w.x, acc.x);
      acc.y = fmaf(xv, w.y, acc.y);
      acc.z = fmaf(xv, w.z, acc.z);
      acc.w = fmaf(xv, w.w, acc.w);
    }
    P4[g] = acc;
  }
}

__device__ __forceinline__ float csum4(const float* part, int N, int j) {
  return (part[j] + part[N + j]) + (part[2 * N + j] + part[3 * N + j]);
}

// ---------------------------------------------------------------------------
// conditioning network for all frames (parallel): grid (64 batch, 100 frames)
__global__ __launch_bounds__(256)
void cond_kernel(const float* __restrict__ feat, const float* __restrict__ gf) {
  __shared__ __align__(16) float s_part[4 * 512];
  __shared__ float s_x[336];
  __shared__ float s_y[336];
  const int b = blockIdx.x, f = blockIdx.y, tid = threadIdx.x;

  for (int j = tid; j < 80; j += 256)  s_x[j]      = feat[(b * 80 + j) * NFRAMES + f];
  for (int j = tid; j < 256; j += 256) s_x[80 + j] = gf[b * 256 + j];
  __syncthreads();
  gemv_part(g_wc + OFFC_C1, s_x, 336, 336, s_part);
  __syncthreads();
  for (int j = tid; j < 336; j += 256) s_y[j] = tanhf(csum4(s_part, 336, j));
  __syncthreads();
  gemv_part(g_wc + OFFC_C2, s_y, 336, 336, s_part);
  __syncthreads();
  for (int j = tid; j < 336; j += 256) s_x[j] = tanhf(csum4(s_part, 336, j));
  __syncthreads();
  gemv_part(g_wc + OFFC_C3, s_x, 336, 512, s_part);
  __syncthreads();
  float* dst = g_cond + (f * NB + b) * 512;
  for (int j = tid; j < 512; j += 256) dst[j] = tanhf(csum4(s_part, 512, j));
}

// ---------------------------------------------------------------------------
// main sequential kernel: one CTA per batch row, 1024 threads.
// dynamic smem: part[32 * 768] floats (96 KB)
extern __shared__ float s_part[];

__global__ __launch_bounds__(NTHREADS, 1)
void main_kernel(const float* __restrict__ prev0,
                 const int*   __restrict__ periods,
                 const float* __restrict__ gain_w,
                 const float* __restrict__ gain_b,
                 const float* __restrict__ pg_w,
                 const float* __restrict__ pg_b,
                 float*       __restrict__ outp) {
  __shared__ float s_x[1152];
  __shared__ float s_xg[768], s_hg[768];
  __shared__ float s_prev[256], s_s1[256], s_s2[256], s_s3[256], s_s4[260];
  __shared__ float s_fw[256], s_fw2[256], s_o1[256], s_o2[256], s_o3[256], s_sk[256];
  __shared__ float s_pl[68], s_psub[64], s_pg[4], s_gain[2], s_out[64];

  const int b = blockIdx.x, tid = threadIdx.x;

  if (tid < 256) {
    s_prev[tid] = prev0[b * 256 + tid];
    s_s1[tid] = 0.f; s_s2[tid] = 0.f; s_s3[tid] = 0.f;
    s_s4[tid] = 0.f;
  }
  if (tid < 4) s_s4[256 + tid] = 0.f;
  __syncthreads();

  const float gb0 = gain_b[0];

  for (int f = 0; f < NFRAMES; ++f) {
    const int per = periods[b * NFRAMES + f];
    const float* condf = g_cond + (f * NB + b) * 512;

    for (int i = 0; i < 4; ++i) {
      const float* sf = condf + i * 128;

      // ---- gain = exp(sf . gain_w + b) (warp 0)
      if (tid < 32) {
        float d = 0.f;
        for (int k = tid; k < 128; k += 32) d = fmaf(sf[k], gain_w[k], d);
#pragma unroll
        for (int o = 16; o; o >>= 1) d += __shfl_xor_sync(0xffffffffu, d, o);
        if (tid == 0) {
          float g = expf(d + gb0);
          s_gain[0] = g;
          s_gain[1] = 1.0f / (1e-5f + g);
        }
      }
      __syncthreads();
      const float ginv = s_gain[1];

      // ---- pitch-lag gather + scaling; prev_sub
      if (tid < 68) {
        int idx = 256 - per + tid - 2;
        if (idx >= 256) idx -= per;
        s_pl[tid] = s_prev[idx] * ginv;
      } else if (tid >= 128 && tid < 192) {
        s_psub[tid - 128] = s_prev[tid + 64] * ginv;  // prev[192..255]
      }
      __syncthreads();

      // ---- assemble fw input: [sf(128), psub(64), pl(68), s4(260), pad] = 544
      if (tid < 128)       s_x[tid] = sf[tid];
      else if (tid < 192)  s_x[tid] = s_psub[tid - 128];
      else if (tid < 256)  s_x[tid] = s_pl[tid - 192];
      else if (tid < 260)  s_x[tid] = s_pl[64 + (tid - 256)];
      else if (tid < 520)  s_x[tid] = s_s4[tid - 260];
      else if (tid < 544)  s_x[tid] = 0.f;
      __syncthreads();

      // s4 <- sif (copy of x[0:260]); runs alongside fw gemv (both read s_x)
      if (tid < 260) s_s4[tid] = s_x[tid];

      gemv32<544, 256>(g_wh + OFFH_FW, s_x, s_part);
      __syncthreads();
      if (tid < 256) s_fw[tid] = tanhf(csum32(s_part, 256, tid));
      __syncthreads();

      gemv32<256, 256>(g_wh + OFFH_FWGLU, s_fw, s_part);
      __syncthreads();
      if (tid < 256) s_fw2[tid] = s_fw[tid] * sigmoidf_(csum32(s_part, 256, tid));
      __syncthreads();

      // ---- pg (4 warps)
      if (tid < 128) {
        int w = tid >> 5, l = tid & 31;
        float d = 0.f;
        for (int k = l; k < 256; k += 32) d = fmaf(s_fw2[k], pg_w[w * 256 + k], d);
#pragma unroll
        for (int o = 16; o; o >>= 1) d += __shfl_xor_sync(0xffffffffu, d, o);
        if (l == 0) s_pg[w] = sigmoidf_(d + pg_b[w]) + 1e-5f;
      }
      __syncthreads();

      // ---- GRU1 input: [fw2(256), pg0*pl2(64), psub(64)] = 384
      if (tid < 256)       s_x[tid] = s_fw2[tid];
      else if (tid < 320)  s_x[tid] = s_pg[0] * s_pl[2 + (tid - 256)];
      else if (tid < 384)  s_x[tid] = s_psub[tid - 320];
      __syncthreads();
      gemv32<384, 768>(g_wh + OFFH_G1IH, s_x, s_part);
      __syncthreads();
      { int j = tid; if (j < 768) s_xg[j] = csum32(s_part, 768, j); }
      __syncthreads();
      gemv32<256, 768>(g_wh + OFFH_G1HH, s_s1, s_part);
      __syncthreads();
      { int j = tid; if (j < 768) s_hg[j] = csum32(s_part, 768, j); }
      __syncthreads();
      if (tid < 256) {
        float r = sigmoidf_(s_xg[tid] + s_hg[tid]);
        float z = sigmoidf_(s_xg[256 + tid] + s_hg[256 + tid]);
        float n = tanhf(s_xg[512 + tid] + r * s_hg[512 + tid]);
        s_s1[tid] = (1.f - z) * n + z * s_s1[tid];
      }
      __syncthreads();
      gemv32<256, 256>(g_wh + OFFH_GLU1, s_s1, s_part);
      __syncthreads();
      if (tid < 256) s_o1[tid] = s_s1[tid] * sigmoidf_(csum32(s_part, 256, tid));
      __syncthreads();

      // ---- GRU2
      if (tid < 256)       s_x[tid] = s_o1[tid];
      else if (tid < 320)  s_x[tid] = s_pg[1] * s_pl[2 + (tid - 256)];
      else if (tid < 384)  s_x[tid] = s_psub[tid - 320];
      __syncthreads();
      gemv32<384, 768>(g_wh + OFFH_G2IH, s_x, s_part);
      __syncthreads();
      { int j = tid; if (j < 768) s_xg[j] = csum32(s_part, 768, j); }
      __syncthreads();
      gemv32<256, 768>(g_wh + OFFH_G2HH, s_s2, s_part);
      __syncthreads();
      { int j = tid; if (j < 768) s_hg[j] = csum32(s_part, 768, j); }
      __syncthreads();
      if (tid < 256) {
        float r = sigmoidf_(s_xg[tid] + s_hg[tid]);
        float z = sigmoidf_(s_xg[256 + tid] + s_hg[256 + tid]);
        float n = tanhf(s_xg[512 + tid] + r * s_hg[512 + tid]);
        s_s2[tid] = (1.f - z) * n + z * s_s2[tid];
      }
      __syncthreads();
      gemv32<256, 256>(g_wh + OFFH_GLU2, s_s2, s_part);
      __syncthreads();
      if (tid < 256) s_o2[tid] = s_s2[tid] * sigmoidf_(csum32(s_part, 256, tid));
      __syncthreads();

      // ---- GRU3
      if (tid < 256)       s_x[tid] = s_o2[tid];
      else if (tid < 320)  s_x[tid] = s_pg[2] * s_pl[2 + (tid - 256)];
      else if (tid < 384)  s_x[tid] = s_psub[tid - 320];
      __syncthreads();
      gemv32<384, 768>(g_wh + OFFH_G3IH, s_x, s_part);
      __syncthreads();
      { int j = tid; if (j < 768) s_xg[j] = csum32(s_part, 768, j); }
      __syncthreads();
      gemv32<256, 768>(g_wh + OFFH_G3HH, s_s3, s_part);
      __syncthreads();
      { int j = tid; if (j < 768) s_hg[j] = csum32(s_part, 768, j); }
      __syncthreads();
      if (tid < 256) {
        float r = sigmoidf_(s_xg[tid] + s_hg[tid]);
        float z = sigmoidf_(s_xg[256 + tid] + s_hg[256 + tid]);
        float n = tanhf(s_xg[512 + tid] + r * s_hg[512 + tid]);
        s_s3[tid] = (1.f - z) * n + z * s_s3[tid];
      }
      __syncthreads();
      gemv32<256, 256>(g_wh + OFFH_GLU3, s_s3, s_part);
      __syncthreads();
      if (tid < 256) s_o3[tid] = s_s3[tid] * sigmoidf_(csum32(s_part, 256, tid));
      __syncthreads();

      // ---- skip input: [o1,o2,o3,fw2,pg3*pl2,psub] = 1152
      if (tid < 256)        s_x[tid] = s_o1[tid];
      else if (tid < 512)   s_x[tid] = s_o2[tid - 256];
      else if (tid < 768)   s_x[tid] = s_o3[tid - 512];
      else                  s_x[tid] = s_fw2[tid - 768];
      if (tid < 64)         s_x[1024 + tid] = s_pg[3] * s_pl[2 + tid];
      else if (tid < 128)   s_x[1024 + tid] = s_psub[tid - 64];
      __syncthreads();
      gemv32<1152, 256>(g_wh + OFFH_SKIP, s_x, s_part);
      __syncthreads();
      if (tid < 256) s_sk[tid] = tanhf(csum32(s_part, 256, tid));
      __syncthreads();
      gemv32<256, 256>(g_wh + OFFH_SKIPGLU, s_sk, s_part);
      __syncthreads();
      if (tid < 256) s_x[tid] = s_sk[tid] * sigmoidf_(csum32(s_part, 256, tid));
      __syncthreads();

      // ---- out = tanh(sk2 @ out_w^T) * gain
      gemv32<256, 64>(g_wh + OFFH_OUT, s_x, s_part);
      __syncthreads();
      if (tid < 64) {
        float v = tanhf(csum32(s_part, 64, tid)) * s_gain[0];
        s_out[tid] = v;
        outp[b * 25600 + f * 256 + i * 64 + tid] = v;
      }
      __syncthreads();

      // ---- prev = [prev[64:], out]
      float pv = 0.f;
      if (tid < 256) pv = (tid < 192) ? s_prev[tid + 64] : s_out[tid - 192];
      __syncthreads();
      if (tid < 256) s_prev[tid] = pv;
      __syncthreads();
    }
  }
}

// ---------------------------------------------------------------------------
extern "C" void kernel_launch(void* const* d_in, const int* in_sizes, int n_in,
                              void* d_out, int out_size) {
  (void)in_sizes; (void)n_in; (void)out_size;
  const float* features = (const float*)d_in[0];
  const float* gfeat    = (const float*)d_in[1];
  const float* prev     = (const float*)d_in[2];
  const int*   periods  = (const int*)d_in[3];
  const float* cond_w1  = (const float*)d_in[4];
  const float* cond_w2  = (const float*)d_in[5];
  const float* cond_w3  = (const float*)d_in[6];
  const float* gain_w   = (const float*)d_in[7];
  const float* gain_b   = (const float*)d_in[8];
  const float* fw_w     = (const float*)d_in[9];
  const float* fw_glu_w = (const float*)d_in[10];
  const float* pg_w     = (const float*)d_in[11];
  const float* pg_b     = (const float*)d_in[12];
  const float* g1ih     = (const float*)d_in[13];
  const float* g1hh     = (const float*)d_in[14];
  const float* g2ih     = (const float*)d_in[15];
  const float* g2hh     = (const float*)d_in[16];
  const float* g3ih     = (const float*)d_in[17];
  const float* g3hh     = (const float*)d_in[18];
  const float* glu1     = (const float*)d_in[19];
  const float* glu2     = (const float*)d_in[20];
  const float* glu3     = (const float*)d_in[21];
  const float* skip_w   = (const float*)d_in[22];
  const float* skipglu  = (const float*)d_in[23];
  const float* out_w    = (const float*)d_in[24];

  __half* wh = nullptr;
  float*  wc = nullptr;
  cudaGetSymbolAddress((void**)&wh, g_wh);
  cudaGetSymbolAddress((void**)&wc, g_wc);

  auto tph = [&](const float* src, int off, int O, int I, int Ipad) {
    int tot = O * Ipad;
    transpose_h_k<<<(tot + 255) / 256, 256>>>(src, wh + off, O, I, Ipad);
  };
  auto tpc = [&](const float* src, int off, int O, int I) {
    int tot = O * I;
    transpose_k<<<(tot + 255) / 256, 256>>>(src, wc + off, O, I);
  };

  tph(fw_w,     OFFH_FW,      256, 520, 544);
  tph(fw_glu_w, OFFH_FWGLU,   256, 256, 256);
  tph(g1ih,     OFFH_G1IH,    768, 384, 384);
  tph(g1hh,     OFFH_G1HH,    768, 256, 256);
  tph(g2ih,     OFFH_G2IH,    768, 384, 384);
  tph(g2hh,     OFFH_G2HH,    768, 256, 256);
  tph(g3ih,     OFFH_G3IH,    768, 384, 384);
  tph(g3hh,     OFFH_G3HH,    768, 256, 256);
  tph(glu1,     OFFH_GLU1,    256, 256, 256);
  tph(glu2,     OFFH_GLU2,    256, 256, 256);
  tph(glu3,     OFFH_GLU3,    256, 256, 256);
  tph(skip_w,   OFFH_SKIP,    256, 1152, 1152);
  tph(skipglu,  OFFH_SKIPGLU, 256, 256, 256);
  tph(out_w,    OFFH_OUT,     64,  256, 256);
  tpc(cond_w1,  OFFC_C1,      336, 336);
  tpc(cond_w2,  OFFC_C2,      336, 336);
  tpc(cond_w3,  OFFC_C3,      512, 336);

  dim3 cg(NB, NFRAMES);
  cond_kernel<<<cg, 256>>>(features, gfeat);

  const int dyn_smem = 32 * 768 * (int)sizeof(float);  // 96 KB
  static int attr_done = 0;
  if (!attr_done) {
    cudaFuncSetAttribute(main_kernel, cudaFuncAttributeMaxDynamicSharedMemorySize, dyn_smem);
    attr_done = 1;
  }
  main_kernel<<<NB, NTHREADS, dyn_smem>>>(prev, periods, gain_w, gain_b, pg_w, pg_b,
                                          (float*)d_out);
}

// round 7
// speedup vs baseline: 2.5431x; 1.0719x over previous
#include <cuda_runtime.h>
#include <cuda_fp16.h>
#include <stdint.h>
#include <math.h>

// ----------------------------------------------------------------------------
// FARGAN vocoder. Round 5: 2-CTA clusters per batch row (128 CTAs on 148 SMs).
// Each CTA computes half of every GEMV's outputs; GRU gate columns permuted so
// each CTA owns full (r,z,n) triplets for 128 of the 256 state entries.
// Activation halves exchanged via DSMEM (st.shared::cluster) + cluster barrier.
// fp16 K-major weights, fp32 accumulate, 1024 threads/CTA.
// ----------------------------------------------------------------------------

#define NFRAMES 100
#define NB      64
#define NTHREADS 1024

__device__ __forceinline__ float sigmoidf_(float x) { return 1.0f / (1.0f + expf(-x)); }

__device__ __forceinline__ uint32_t s2u_(const void* p) {
  uint32_t a;
  asm("{ .reg .u64 t; cvta.to.shared.u64 t, %1; cvt.u32.u64 %0, t; }" : "=r"(a) : "l"(p));
  return a;
}
__device__ __forceinline__ uint32_t mapa_u_(uint32_t a, uint32_t r) {
  uint32_t d;
  asm("mapa.shared::cluster.u32 %0, %1, %2;" : "=r"(d) : "r"(a), "r"(r));
  return d;
}
__device__ __forceinline__ void st_peer_(uint32_t a, float v) {
  asm volatile("st.shared::cluster.f32 [%0], %1;" :: "r"(a), "f"(v));
}
#define CLUSTER_SYNC_() do { \
  asm volatile("barrier.cluster.arrive.aligned;" ::: "memory"); \
  asm volatile("barrier.cluster.wait.aligned;" ::: "memory"); \
} while (0)

// fp16 reorganized weights: per matrix two slices, each [Kpad][O/2]
enum : int {
  OFFH_FW      = 0,                          // 544 x 256
  OFFH_FWGLU   = OFFH_FW      + 544 * 256,   // 256 x 256
  OFFH_G1IH    = OFFH_FWGLU   + 256 * 256,   // 384 x 768
  OFFH_G1HH    = OFFH_G1IH    + 384 * 768,   // 256 x 768
  OFFH_G2IH    = OFFH_G1HH    + 256 * 768,
  OFFH_G2HH    = OFFH_G2IH    + 384 * 768,
  OFFH_G3IH    = OFFH_G2HH    + 256 * 768,
  OFFH_G3HH    = OFFH_G3IH    + 384 * 768,
  OFFH_GLU1    = OFFH_G3HH    + 256 * 768,
  OFFH_GLU2    = OFFH_GLU1    + 256 * 256,
  OFFH_GLU3    = OFFH_GLU2    + 256 * 256,
  OFFH_SKIP    = OFFH_GLU3    + 256 * 256,   // 1152 x 256
  OFFH_SKIPGLU = OFFH_SKIP    + 1152 * 256,
  WH_TOTAL     = OFFH_SKIPGLU + 256 * 256
};

enum : int {
  OFFC_C1  = 0,
  OFFC_C2  = OFFC_C1 + 336 * 336,
  OFFC_C3  = OFFC_C2 + 336 * 336,
  WC_TOTAL = OFFC_C3 + 336 * 512
};

__device__ __half g_wh[WH_TOTAL];
__device__ float  g_wc[WC_TOTAL];
__device__ float  g_cond[NFRAMES * NB * 512];

// ---------------------------------------------------------------------------
__global__ void transpose_k(const float* __restrict__ src, float* __restrict__ dst,
                            int O, int I) {
  int idx = blockIdx.x * blockDim.x + threadIdx.x;
  if (idx < O * I) {
    int i = idx / O;
    int o = idx % O;
    dst[idx] = src[o * I + i];
  }
}

// reorg: src[O][I] -> two half slices dst[r][Ipad][O/2], fp16.
// mode 0: owner r = o/(O/2), col = o%(O/2)
// mode 1 (GRU, O=768): s=o%256,g=o/256; r=s/128, col=g*128+(s%128)
__global__ void reorg_h(const float* __restrict__ src, __half* __restrict__ dst,
                        int O, int I, int Ipad, int mode) {
  int idx = blockIdx.x * blockDim.x + threadIdx.x;
  if (idx >= O * Ipad) return;
  int i = idx / O;
  int o = idx % O;
  int Oh = O >> 1;
  int r, c;
  if (mode == 0) { r = o / Oh; c = o % Oh; }
  else { int s = o & 255, g = o >> 8; r = (s >> 7); c = g * 128 + (s & 127); }
  float v = (i < I) ? src[o * I + i] : 0.f;
  dst[(size_t)r * ((size_t)Ipad * Oh) + (size_t)i * Oh + c] = __float2half(v);
}

// ---------------------------------------------------------------------------
// fp16 GEMV partial, 1024 threads = 32 K-chunks x 32 lanes. Wh K-major [K][Nh].
template <int K, int Nh>
__device__ __forceinline__ void gemv32(const __half* __restrict__ Wh,
                                       const float* __restrict__ xs,
                                       float* __restrict__ part) {
  const int tid  = threadIdx.x;
  const int kc   = tid >> 5;
  const int lane = tid & 31;
  constexpr int Kc = K / 32;
  constexpr int NV = Nh / 8;
  constexpr int NG = (NV + 31) / 32;

  const float* xk = xs + kc * Kc;
  const float4* __restrict__ W4 =
      reinterpret_cast<const float4*>(Wh) + (size_t)(kc * Kc) * NV;

  float acc[NG][8];
#pragma unroll
  for (int ng = 0; ng < NG; ++ng)
#pragma unroll
    for (int j = 0; j < 8; ++j) acc[ng][j] = 0.f;

#pragma unroll 4
  for (int k = 0; k < Kc; ++k) {
    const float xv = xk[k];
    const float4* wr = W4 + (size_t)k * NV + lane;
#pragma unroll
    for (int ng = 0; ng < NG; ++ng) {
      if (NV >= 32 * (ng + 1) || lane + ng * 32 < NV) {
        float4 h8 = wr[ng * 32];
        const __half2* hp = reinterpret_cast<const __half2*>(&h8);
#pragma unroll
        for (int j = 0; j < 4; ++j) {
          float2 f = __half22float2(hp[j]);
          acc[ng][2 * j]     = fmaf(xv, f.x, acc[ng][2 * j]);
          acc[ng][2 * j + 1] = fmaf(xv, f.y, acc[ng][2 * j + 1]);
        }
      }
    }
  }

  float4* P4 = reinterpret_cast<float4*>(part + kc * Nh);
#pragma unroll
  for (int ng = 0; ng < NG; ++ng) {
    if (NV >= 32 * (ng + 1) || lane + ng * 32 < NV) {
      int g = lane + ng * 32;
      P4[2 * g]     = make_float4(acc[ng][0], acc[ng][1], acc[ng][2], acc[ng][3]);
      P4[2 * g + 1] = make_float4(acc[ng][4], acc[ng][5], acc[ng][6], acc[ng][7]);
    }
  }
}

__device__ __forceinline__ float csum32(const float* __restrict__ part, int N, int j) {
  float s = 0.f;
#pragma unroll
  for (int c = 0; c < 32; c += 4) {
    float a = part[c * N + j]       + part[(c + 1) * N + j];
    float b = part[(c + 2) * N + j] + part[(c + 3) * N + j];
    s += (a + b);
  }
  return s;
}

// ---------------------------------------------------------------------------
// fp32 GEMV for conditioning net
__device__ __forceinline__ void gemv_part(const float* __restrict__ Wt,
                                          const float* __restrict__ xs,
                                          int K, int N, float* part) {
  const int tid = threadIdx.x;
  const int kc  = tid >> 6;
  const int g0  = tid & 63;
  const int Kc  = K >> 2;
  const int G   = N >> 2;
  const float4* __restrict__ W4 = reinterpret_cast<const float4*>(Wt) + (size_t)(kc * Kc) * G;
  const float*  __restrict__ xk = xs + kc * Kc;
  float4* P4 = reinterpret_cast<float4*>(part + kc * N);
  for (int g = g0; g < G; g += 64) {
    float4 acc = make_float4(0.f, 0.f, 0.f, 0.f);
    const float4* wp = W4 + g;
#pragma unroll 4
    for (int k = 0; k < Kc; ++k) {
      const float xv = xk[k];
      const float4 w = wp[(size_t)k * G];
      acc.x = fmaf(xv, w.x, acc.x);
      acc.y = fmaf(xv, w.y, acc.y);
      acc.z = fmaf(xv, w.z, acc.z);
      acc.w = fmaf(xv, w.w, acc.w);
    }
    P4[g] = acc;
  }
}

__device__ __forceinline__ float csum4(const float* part, int N, int j) {
  return (part[j] + part[N + j]) + (part[2 * N + j] + part[3 * N + j]);
}

__global__ __launch_bounds__(256)
void cond_kernel(const float* __restrict__ feat, const float* __restrict__ gf) {
  __shared__ __align__(16) float s_part[4 * 512];
  __shared__ float s_x[336];
  __shared__ float s_y[336];
  const int b = blockIdx.x, f = blockIdx.y, tid = threadIdx.x;

  for (int j = tid; j < 80; j += 256)  s_x[j]      = feat[(b * 80 + j) * NFRAMES + f];
  for (int j = tid; j < 256; j += 256) s_x[80 + j] = gf[b * 256 + j];
  __syncthreads();
  gemv_part(g_wc + OFFC_C1, s_x, 336, 336, s_part);
  __syncthreads();
  for (int j = tid; j < 336; j += 256) s_y[j] = tanhf(csum4(s_part, 336, j));
  __syncthreads();
  gemv_part(g_wc + OFFC_C2, s_y, 336, 336, s_part);
  __syncthreads();
  for (int j = tid; j < 336; j += 256) s_x[j] = tanhf(csum4(s_part, 336, j));
  __syncthreads();
  gemv_part(g_wc + OFFC_C3, s_x, 336, 512, s_part);
  __syncthreads();
  float* dst = g_cond + (f * NB + b) * 512;
  for (int j = tid; j < 512; j += 256) dst[j] = tanhf(csum4(s_part, 512, j));
}

// ---------------------------------------------------------------------------
// main kernel: clusters of 2 CTAs; cluster c handles batch row c. rank = half.
extern __shared__ float s_part[];  // 32 * 384 floats

__global__ __launch_bounds__(NTHREADS, 1) __cluster_dims__(2, 1, 1)
void main_kernel(const float* __restrict__ prev0,
                 const int*   __restrict__ periods,
                 const float* __restrict__ gain_w,
                 const float* __restrict__ gain_b,
                 const float* __restrict__ pg_w,
                 const float* __restrict__ pg_b,
                 const float* __restrict__ out_w,
                 float*       __restrict__ outp) {
  __shared__ float s_x[1152];
  __shared__ float s_xg[384], s_hg[384];
  __shared__ float s_prev[256], s_s1[256], s_s2[256], s_s3[256], s_s4[260];
  __shared__ float s_fw[256], s_fw2[256], s_o1[256], s_o2[256], s_o3[256];
  __shared__ float s_sk[256], s_sk2[256];
  __shared__ float s_pl[68], s_psub[64], s_pg[4], s_gain[2], s_out[64];

  const int tid  = threadIdx.x;
  const int rank = blockIdx.x & 1;
  const int b    = blockIdx.x >> 1;
  const uint32_t pr = rank ^ 1;

  if (tid < 256) {
    s_prev[tid] = prev0[b * 256 + tid];
    s_s1[tid] = 0.f; s_s2[tid] = 0.f; s_s3[tid] = 0.f;
    s_s4[tid] = 0.f;
  }
  if (tid < 4) s_s4[256 + tid] = 0.f;
  __syncthreads();

  const float gb0 = gain_b[0];

  for (int f = 0; f < NFRAMES; ++f) {
    const int per = periods[b * NFRAMES + f];
    const float* condf = g_cond + (f * NB + b) * 512;

    for (int i = 0; i < 4; ++i) {
      const float* sf = condf + i * 128;

      // ---- gain (redundant in both CTAs, warp 0)
      if (tid < 32) {
        float d = 0.f;
        for (int k = tid; k < 128; k += 32) d = fmaf(sf[k], gain_w[k], d);
#pragma unroll
        for (int o = 16; o; o >>= 1) d += __shfl_xor_sync(0xffffffffu, d, o);
        if (tid == 0) {
          float g = expf(d + gb0);
          s_gain[0] = g;
          s_gain[1] = 1.0f / (1e-5f + g);
        }
      }
      __syncthreads();
      const float ginv = s_gain[1];

      // ---- pitch-lag gather (redundant)
      if (tid < 68) {
        int idx = 256 - per + tid - 2;
        if (idx >= 256) idx -= per;
        s_pl[tid] = s_prev[idx] * ginv;
      } else if (tid >= 128 && tid < 192) {
        s_psub[tid - 128] = s_prev[tid + 64] * ginv;
      }
      __syncthreads();

      // ---- fw input: [sf(128), psub(64), pl(68), s4(260), pad] = 544
      if (tid < 128)       s_x[tid] = sf[tid];
      else if (tid < 192)  s_x[tid] = s_psub[tid - 128];
      else if (tid < 256)  s_x[tid] = s_pl[tid - 192];
      else if (tid < 260)  s_x[tid] = s_pl[64 + (tid - 256)];
      else if (tid < 520)  s_x[tid] = s_s4[tid - 260];
      else if (tid < 544)  s_x[tid] = 0.f;
      __syncthreads();
      if (tid < 260) s_s4[tid] = s_x[tid];

      gemv32<544, 128>(g_wh + OFFH_FW + rank * 544 * 128, s_x, s_part);
      __syncthreads();
      if (tid < 128) {
        int j = rank * 128 + tid;
        float v = tanhf(csum32(s_part, 128, tid));
        s_fw[j] = v; st_peer_(mapa_u_(s2u_(&s_fw[j]), pr), v);
      }
      CLUSTER_SYNC_();

      gemv32<256, 128>(g_wh + OFFH_FWGLU + rank * 256 * 128, s_fw, s_part);
      __syncthreads();
      if (tid < 128) {
        int j = rank * 128 + tid;
        float v = s_fw[j] * sigmoidf_(csum32(s_part, 128, tid));
        s_fw2[j] = v; st_peer_(mapa_u_(s2u_(&s_fw2[j]), pr), v);
      }
      CLUSTER_SYNC_();

      // ---- pg (redundant, 4 warps)
      if (tid < 128) {
        int w = tid >> 5, l = tid & 31;
        float d = 0.f;
        for (int k = l; k < 256; k += 32) d = fmaf(s_fw2[k], pg_w[w * 256 + k], d);
#pragma unroll
        for (int o = 16; o; o >>= 1) d += __shfl_xor_sync(0xffffffffu, d, o);
        if (l == 0) s_pg[w] = sigmoidf_(d + pg_b[w]) + 1e-5f;
      }
      __syncthreads();

      // ================= GRU macro =================
#define GRU_STAGE(SRC, OFF_IH, OFF_HH, SSTATE, PGI)                            \
      if (tid < 256)       s_x[tid] = SRC[tid];                                \
      else if (tid < 320)  s_x[tid] = s_pg[PGI] * s_pl[2 + (tid - 256)];       \
      else if (tid < 384)  s_x[tid] = s_psub[tid - 320];                       \
      __syncthreads();                                                         \
      gemv32<384, 384>(g_wh + OFF_IH + rank * 384 * 384, s_x, s_part);         \
      __syncthreads();                                                         \
      if (tid < 384) s_xg[tid] = csum32(s_part, 384, tid);                     \
      __syncthreads();                                                         \
      gemv32<256, 384>(g_wh + OFF_HH + rank * 256 * 384, SSTATE, s_part);      \
      __syncthreads();                                                         \
      if (tid < 384) s_hg[tid] = csum32(s_part, 384, tid);                     \
      __syncthreads();                                                         \
      if (tid < 128) {                                                         \
        int j = rank * 128 + tid;                                              \
        float r = sigmoidf_(s_xg[tid] + s_hg[tid]);                            \
        float z = sigmoidf_(s_xg[128 + tid] + s_hg[128 + tid]);                \
        float n = tanhf(s_xg[256 + tid] + r * s_hg[256 + tid]);                \
        float v = (1.f - z) * n + z * SSTATE[j];                               \
        SSTATE[j] = v; st_peer_(mapa_u_(s2u_(&SSTATE[j]), pr), v);             \
      }                                                                        \
      CLUSTER_SYNC_();

#define GLU_STAGE(OFF_GLU, SSTATE, DST)                                        \
      gemv32<256, 128>(g_wh + OFF_GLU + rank * 256 * 128, SSTATE, s_part);     \
      __syncthreads();                                                         \
      if (tid < 128) {                                                         \
        int j = rank * 128 + tid;                                              \
        float v = SSTATE[j] * sigmoidf_(csum32(s_part, 128, tid));             \
        DST[j] = v; st_peer_(mapa_u_(s2u_(&DST[j]), pr), v);                   \
      }                                                                        \
      CLUSTER_SYNC_();

      GRU_STAGE(s_fw2, OFFH_G1IH, OFFH_G1HH, s_s1, 0)
      GLU_STAGE(OFFH_GLU1, s_s1, s_o1)
      GRU_STAGE(s_o1, OFFH_G2IH, OFFH_G2HH, s_s2, 1)
      GLU_STAGE(OFFH_GLU2, s_s2, s_o2)
      GRU_STAGE(s_o2, OFFH_G3IH, OFFH_G3HH, s_s3, 2)
      GLU_STAGE(OFFH_GLU3, s_s3, s_o3)
#undef GRU_STAGE
#undef GLU_STAGE

      // ---- skip input: [o1,o2,o3,fw2,pg3*pl2,psub] = 1152 (replicated)
      if (tid < 256)        s_x[tid] = s_o1[tid];
      else if (tid < 512)   s_x[tid] = s_o2[tid - 256];
      else if (tid < 768)   s_x[tid] = s_o3[tid - 512];
      else                  s_x[tid] = s_fw2[tid - 768];
      if (tid < 64)         s_x[1024 + tid] = s_pg[3] * s_pl[2 + tid];
      else if (tid < 128)   s_x[1024 + tid] = s_psub[tid - 64];
      __syncthreads();
      gemv32<1152, 128>(g_wh + OFFH_SKIP + rank * 1152 * 128, s_x, s_part);
      __syncthreads();
      if (tid < 128) {
        int j = rank * 128 + tid;
        float v = tanhf(csum32(s_part, 128, tid));
        s_sk[j] = v; st_peer_(mapa_u_(s2u_(&s_sk[j]), pr), v);
      }
      CLUSTER_SYNC_();

      gemv32<256, 128>(g_wh + OFFH_SKIPGLU + rank * 256 * 128, s_sk, s_part);
      __syncthreads();
      if (tid < 128) {
        int j = rank * 128 + tid;
        float v = s_sk[j] * sigmoidf_(csum32(s_part, 128, tid));
        s_sk2[j] = v; st_peer_(mapa_u_(s2u_(&s_sk2[j]), pr), v);
      }
      CLUSTER_SYNC_();

      // ---- out: warp w computes output (rank*32 + w), fp32 weights direct
      {
        const int w = tid >> 5, l = tid & 31;
        const int o = rank * 32 + w;
        const float4* wr = reinterpret_cast<const float4*>(out_w + o * 256) + l * 2;
        const float4* xr = reinterpret_cast<const float4*>(s_sk2) + l * 2;
        float4 wa = wr[0], wb = wr[1];
        float4 xa = xr[0], xb = xr[1];
        float d = wa.x * xa.x + wa.y * xa.y + wa.z * xa.z + wa.w * xa.w
                + wb.x * xb.x + wb.y * xb.y + wb.z * xb.z + wb.w * xb.w;
#pragma unroll
        for (int oo = 16; oo; oo >>= 1) d += __shfl_xor_sync(0xffffffffu, d, oo);
        if (l == 0) {
          float v = tanhf(d) * s_gain[0];
          s_out[o] = v; st_peer_(mapa_u_(s2u_(&s_out[o]), pr), v);
          outp[b * 25600 + f * 256 + i * 64 + o] = v;
        }
      }
      CLUSTER_SYNC_();

      // ---- prev = [prev[64:], out] (replicated)
      float pv = 0.f;
      if (tid < 256) pv = (tid < 192) ? s_prev[tid + 64] : s_out[tid - 192];
      __syncthreads();
      if (tid < 256) s_prev[tid] = pv;
      __syncthreads();
    }
  }
}

// ---------------------------------------------------------------------------
extern "C" void kernel_launch(void* const* d_in, const int* in_sizes, int n_in,
                              void* d_out, int out_size) {
  (void)in_sizes; (void)n_in; (void)out_size;
  const float* features = (const float*)d_in[0];
  const float* gfeat    = (const float*)d_in[1];
  const float* prev     = (const float*)d_in[2];
  const int*   periods  = (const int*)d_in[3];
  const float* cond_w1  = (const float*)d_in[4];
  const float* cond_w2  = (const float*)d_in[5];
  const float* cond_w3  = (const float*)d_in[6];
  const float* gain_w   = (const float*)d_in[7];
  const float* gain_b   = (const float*)d_in[8];
  const float* fw_w     = (const float*)d_in[9];
  const float* fw_glu_w = (const float*)d_in[10];
  const float* pg_w     = (const float*)d_in[11];
  const float* pg_b     = (const float*)d_in[12];
  const float* g1ih     = (const float*)d_in[13];
  const float* g1hh     = (const float*)d_in[14];
  const float* g2ih     = (const float*)d_in[15];
  const float* g2hh     = (const float*)d_in[16];
  const float* g3ih     = (const float*)d_in[17];
  const float* g3hh     = (const float*)d_in[18];
  const float* glu1     = (const float*)d_in[19];
  const float* glu2     = (const float*)d_in[20];
  const float* glu3     = (const float*)d_in[21];
  const float* skip_w   = (const float*)d_in[22];
  const float* skipglu  = (const float*)d_in[23];
  const float* out_w    = (const float*)d_in[24];

  __half* wh = nullptr;
  float*  wc = nullptr;
  cudaGetSymbolAddress((void**)&wh, g_wh);
  cudaGetSymbolAddress((void**)&wc, g_wc);

  auto rg = [&](const float* src, int off, int O, int I, int Ipad, int mode) {
    int tot = O * Ipad;
    reorg_h<<<(tot + 255) / 256, 256>>>(src, wh + off, O, I, Ipad, mode);
  };
  auto tpc = [&](const float* src, int off, int O, int I) {
    int tot = O * I;
    transpose_k<<<(tot + 255) / 256, 256>>>(src, wc + off, O, I);
  };

  rg(fw_w,     OFFH_FW,      256, 520, 544, 0);
  rg(fw_glu_w, OFFH_FWGLU,   256, 256, 256, 0);
  rg(g1ih,     OFFH_G1IH,    768, 384, 384, 1);
  rg(g1hh,     OFFH_G1HH,    768, 256, 256, 1);
  rg(g2ih,     OFFH_G2IH,    768, 384, 384, 1);
  rg(g2hh,     OFFH_G2HH,    768, 256, 256, 1);
  rg(g3ih,     OFFH_G3IH,    768, 384, 384, 1);
  rg(g3hh,     OFFH_G3HH,    768, 256, 256, 1);
  rg(glu1,     OFFH_GLU1,    256, 256, 256, 0);
  rg(glu2,     OFFH_GLU2,    256, 256, 256, 0);
  rg(glu3,     OFFH_GLU3,    256, 256, 256, 0);
  rg(skip_w,   OFFH_SKIP,    256, 1152, 1152, 0);
  rg(skipglu,  OFFH_SKIPGLU, 256, 256, 256, 0);
  tpc(cond_w1, OFFC_C1,      336, 336);
  tpc(cond_w2, OFFC_C2,      336, 336);
  tpc(cond_w3, OFFC_C3,      512, 336);

  dim3 cg(NB, NFRAMES);
  cond_kernel<<<cg, 256>>>(features, gfeat);

  const int dyn_smem = 32 * 384 * (int)sizeof(float);  // 48 KB
  cudaFuncSetAttribute(main_kernel, cudaFuncAttributeMaxDynamicSharedMemorySize, dyn_smem);
  main_kernel<<<2 * NB, NTHREADS, dyn_smem>>>(prev, periods, gain_w, gain_b,
                                              pg_w, pg_b, out_w, (float*)d_out);
}

// round 8
// speedup vs baseline: 3.5195x; 1.3839x over previous
#include <cuda_runtime.h>
#include <cuda_fp16.h>
#include <stdint.h>
#include <math.h>

// ----------------------------------------------------------------------------
// FARGAN vocoder. Round 7: 4-CTA clusters, 2 batch rows per cluster
// (32 clusters x 4 = 128 CTAs). Each CTA computes 1/4 of every stage's
// outputs for BOTH rows -> chip weight traffic halves (weights reused for
// 2 rows). GRU IH/HH kept as separate gemvs (n-gate needs inn + r*hn) but
// inside one barrier stage. fp16 K-major weights, fp32 accumulate.
// ----------------------------------------------------------------------------

#define NFRAMES 100
#define NB      64
#define NTHREADS 1024

__device__ __forceinline__ float sigmoidf_(float x) { return 1.0f / (1.0f + expf(-x)); }

__device__ __forceinline__ uint32_t s2u_(const void* p) {
  uint32_t a;
  asm("{ .reg .u64 t; cvta.to.shared.u64 t, %1; cvt.u32.u64 %0, t; }" : "=r"(a) : "l"(p));
  return a;
}
__device__ __forceinline__ uint32_t mapa_u_(uint32_t a, uint32_t r) {
  uint32_t d;
  asm("mapa.shared::cluster.u32 %0, %1, %2;" : "=r"(d) : "r"(a), "r"(r));
  return d;
}
__device__ __forceinline__ void st_peer_(uint32_t a, float v) {
  asm volatile("st.shared::cluster.f32 [%0], %1;" :: "r"(a), "f"(v));
}
#define CLUSTER_SYNC_() do { \
  asm volatile("barrier.cluster.arrive.aligned;" ::: "memory"); \
  asm volatile("barrier.cluster.wait.aligned;" ::: "memory"); \
} while (0)

// fp16 weights, 4 rank-slices per matrix: [4][Kpad][Oq]
enum : int {
  OFFH_FW      = 0,                          // 4 x 544 x 64
  OFFH_FWGLU   = OFFH_FW      + 544 * 256,   // 4 x 256 x 64
  OFFH_G1IH    = OFFH_FWGLU   + 256 * 256,   // 4 x 384 x 192
  OFFH_G1HH    = OFFH_G1IH    + 384 * 768,   // 4 x 256 x 192
  OFFH_G2IH    = OFFH_G1HH    + 256 * 768,
  OFFH_G2HH    = OFFH_G2IH    + 384 * 768,
  OFFH_G3IH    = OFFH_G2HH    + 256 * 768,
  OFFH_G3HH    = OFFH_G3IH    + 384 * 768,
  OFFH_GLU1    = OFFH_G3HH    + 256 * 768,
  OFFH_GLU2    = OFFH_GLU1    + 256 * 256,
  OFFH_GLU3    = OFFH_GLU2    + 256 * 256,
  OFFH_SKIP    = OFFH_GLU3    + 256 * 256,   // 4 x 1152 x 64
  OFFH_SKIPGLU = OFFH_SKIP    + 1152 * 256,
  WH_TOTAL     = OFFH_SKIPGLU + 256 * 256
};

enum : int {
  OFFC_C1  = 0,
  OFFC_C2  = OFFC_C1 + 336 * 336,
  OFFC_C3  = OFFC_C2 + 336 * 336,
  WC_TOTAL = OFFC_C3 + 336 * 512
};

__device__ __half g_wh[WH_TOTAL];
__device__ float  g_wc[WC_TOTAL];
__device__ float  g_cond[NFRAMES * NB * 512];

// ---------------------------------------------------------------------------
__global__ void transpose_k(const float* __restrict__ src, float* __restrict__ dst,
                            int O, int I) {
  int idx = blockIdx.x * blockDim.x + threadIdx.x;
  if (idx < O * I) {
    int i = idx / O;
    int o = idx % O;
    dst[idx] = src[o * I + i];
  }
}

// 4-way mode0 reorg: src[O][I] -> dst[4][Ipad][O/4] fp16
__global__ void reorg_h4(const float* __restrict__ src, __half* __restrict__ dst,
                         int O, int I, int Ipad) {
  int idx = blockIdx.x * blockDim.x + threadIdx.x;
  if (idx >= O * Ipad) return;
  int i = idx / O, o = idx % O;
  int Oq = O >> 2;
  int r = o / Oq, c = o % Oq;
  float v = (i < I) ? src[o * I + i] : 0.f;
  dst[((size_t)r * Ipad + i) * Oq + c] = __float2half(v);
}

// 4-way GRU reorg (gate-permuted): w[768][I] -> dst[4][I][192]
// s=o%256, g=o/256; rank=s/64; col=g*64+(s%64)
__global__ void reorg_gru4(const float* __restrict__ src, __half* __restrict__ dst,
                           int I) {
  int idx = blockIdx.x * blockDim.x + threadIdx.x;
  if (idx >= 768 * I) return;
  int i = idx / 768, o = idx % 768;
  int s = o & 255, g = o >> 8;
  int r = s >> 6, c = g * 64 + (s & 63);
  dst[((size_t)r * I + i) * 192 + c] = __float2half(src[o * I + i]);
}

// ---------------------------------------------------------------------------
// 2-row fp16 GEMV partial, 1024 thr = 32 K-chunks x 32 lanes, float2 weights.
// NQ==64: lane = row*16 + v (16 float2 cols per row). NQ==192: both rows,
// groups v=lane and v=32+lane (lane<16). part[(row*32+kc)*NQ + col].
template <int K, int NQ>
__device__ __forceinline__ void gemv2r(const __half* __restrict__ Wh,
                                       const float* __restrict__ xs, int rs,
                                       float* __restrict__ part) {
  const int tid  = threadIdx.x;
  const int kc   = tid >> 5;
  const int lane = tid & 31;
  constexpr int Kc  = K / 32;
  constexpr int NV2 = NQ / 4;
  const float2* __restrict__ W2 =
      reinterpret_cast<const float2*>(Wh) + (size_t)(kc * Kc) * NV2;

  if (NQ == 64) {
    const int row = lane >> 4, v = lane & 15;
    const float* xk = xs + row * rs + kc * Kc;
    float acc[4] = {0.f, 0.f, 0.f, 0.f};
#pragma unroll 4
    for (int k = 0; k < Kc; ++k) {
      const float xv = xk[k];
      float2 hw = W2[k * 16 + v];
      const __half2* hp = reinterpret_cast<const __half2*>(&hw);
      float2 f0 = __half22float2(hp[0]);
      float2 f1 = __half22float2(hp[1]);
      acc[0] = fmaf(xv, f0.x, acc[0]);
      acc[1] = fmaf(xv, f0.y, acc[1]);
      acc[2] = fmaf(xv, f1.x, acc[2]);
      acc[3] = fmaf(xv, f1.y, acc[3]);
    }
    float4* P4 = reinterpret_cast<float4*>(part + (row * 32 + kc) * 64);
    P4[v] = make_float4(acc[0], acc[1], acc[2], acc[3]);
  } else {  // NQ == 192
    const float* xk0 = xs + kc * Kc;
    const float* xk1 = xs + rs + kc * Kc;
    float a0[2][4], a1[2][4];
#pragma unroll
    for (int j = 0; j < 4; ++j) { a0[0][j] = a0[1][j] = a1[0][j] = a1[1][j] = 0.f; }
#pragma unroll 4
    for (int k = 0; k < Kc; ++k) {
      const float x0 = xk0[k], x1 = xk1[k];
      float2 hwa = W2[k * 48 + lane];
      const __half2* hpa = reinterpret_cast<const __half2*>(&hwa);
      float2 fa0 = __half22float2(hpa[0]);
      float2 fa1 = __half22float2(hpa[1]);
      a0[0][0] = fmaf(x0, fa0.x, a0[0][0]); a0[0][1] = fmaf(x0, fa0.y, a0[0][1]);
      a0[0][2] = fmaf(x0, fa1.x, a0[0][2]); a0[0][3] = fmaf(x0, fa1.y, a0[0][3]);
      a0[1][0] = fmaf(x1, fa0.x, a0[1][0]); a0[1][1] = fmaf(x1, fa0.y, a0[1][1]);
      a0[1][2] = fmaf(x1, fa1.x, a0[1][2]); a0[1][3] = fmaf(x1, fa1.y, a0[1][3]);
      if (lane < 16) {
        float2 hwb = W2[k * 48 + 32 + lane];
        const __half2* hpb = reinterpret_cast<const __half2*>(&hwb);
        float2 fb0 = __half22float2(hpb[0]);
        float2 fb1 = __half22float2(hpb[1]);
        a1[0][0] = fmaf(x0, fb0.x, a1[0][0]); a1[0][1] = fmaf(x0, fb0.y, a1[0][1]);
        a1[0][2] = fmaf(x0, fb1.x, a1[0][2]); a1[0][3] = fmaf(x0, fb1.y, a1[0][3]);
        a1[1][0] = fmaf(x1, fb0.x, a1[1][0]); a1[1][1] = fmaf(x1, fb0.y, a1[1][1]);
        a1[1][2] = fmaf(x1, fb1.x, a1[1][2]); a1[1][3] = fmaf(x1, fb1.y, a1[1][3]);
      }
    }
#pragma unroll
    for (int row = 0; row < 2; ++row) {
      float4* P4 = reinterpret_cast<float4*>(part + (row * 32 + kc) * 192);
      P4[lane] = make_float4(a0[row][0], a0[row][1], a0[row][2], a0[row][3]);
      if (lane < 16)
        P4[32 + lane] = make_float4(a1[row][0], a1[row][1], a1[row][2], a1[row][3]);
    }
  }
}

__device__ __forceinline__ float csum2r(const float* __restrict__ part, int NQ,
                                        int row, int j) {
  const float* p = part + (row * 32) * NQ + j;
  float s = 0.f;
#pragma unroll
  for (int c = 0; c < 32; c += 4) {
    float a = p[c * NQ]       + p[(c + 1) * NQ];
    float b = p[(c + 2) * NQ] + p[(c + 3) * NQ];
    s += (a + b);
  }
  return s;
}

// ---------------------------------------------------------------------------
// conditioning net (unchanged)
__device__ __forceinline__ void gemv_part(const float* __restrict__ Wt,
                                          const float* __restrict__ xs,
                                          int K, int N, float* part) {
  const int tid = threadIdx.x;
  const int kc  = tid >> 6;
  const int g0  = tid & 63;
  const int Kc  = K >> 2;
  const int G   = N >> 2;
  const float4* __restrict__ W4 = reinterpret_cast<const float4*>(Wt) + (size_t)(kc * Kc) * G;
  const float*  __restrict__ xk = xs + kc * Kc;
  float4* P4 = reinterpret_cast<float4*>(part + kc * N);
  for (int g = g0; g < G; g += 64) {
    float4 acc = make_float4(0.f, 0.f, 0.f, 0.f);
    const float4* wp = W4 + g;
#pragma unroll 4
    for (int k = 0; k < Kc; ++k) {
      const float xv = xk[k];
      const float4 w = wp[(size_t)k * G];
      acc.x = fmaf(xv, w.x, acc.x);
      acc.y = fmaf(xv, w.y, acc.y);
      acc.z = fmaf(xv, w.z, acc.z);
      acc.w = fmaf(xv, w.w, acc.w);
    }
    P4[g] = acc;
  }
}
__device__ __forceinline__ float csum4(const float* part, int N, int j) {
  return (part[j] + part[N + j]) + (part[2 * N + j] + part[3 * N + j]);
}

__global__ __launch_bounds__(256)
void cond_kernel(const float* __restrict__ feat, const float* __restrict__ gf) {
  __shared__ __align__(16) float s_part[4 * 512];
  __shared__ float s_x[336];
  __shared__ float s_y[336];
  const int b = blockIdx.x, f = blockIdx.y, tid = threadIdx.x;

  for (int j = tid; j < 80; j += 256)  s_x[j]      = feat[(b * 80 + j) * NFRAMES + f];
  for (int j = tid; j < 256; j += 256) s_x[80 + j] = gf[b * 256 + j];
  __syncthreads();
  gemv_part(g_wc + OFFC_C1, s_x, 336, 336, s_part);
  __syncthreads();
  for (int j = tid; j < 336; j += 256) s_y[j] = tanhf(csum4(s_part, 336, j));
  __syncthreads();
  gemv_part(g_wc + OFFC_C2, s_y, 336, 336, s_part);
  __syncthreads();
  for (int j = tid; j < 336; j += 256) s_x[j] = tanhf(csum4(s_part, 336, j));
  __syncthreads();
  gemv_part(g_wc + OFFC_C3, s_x, 336, 512, s_part);
  __syncthreads();
  float* dst = g_cond + (f * NB + b) * 512;
  for (int j = tid; j < 512; j += 256) dst[j] = tanhf(csum4(s_part, 512, j));
}

// ---------------------------------------------------------------------------
// main kernel: 32 clusters of 4 CTAs; cluster q handles rows 2q, 2q+1.
// dynamic smem: partA[2*32*192] + partB[2*32*192] floats (96 KB)
extern __shared__ float s_dyn[];
#define PART_A (s_dyn)
#define PART_B (s_dyn + 2 * 32 * 192)

__global__ __launch_bounds__(NTHREADS, 1) __cluster_dims__(4, 1, 1)
void main_kernel(const float* __restrict__ prev0,
                 const int*   __restrict__ periods,
                 const float* __restrict__ gain_w,
                 const float* __restrict__ gain_b,
                 const float* __restrict__ pg_w,
                 const float* __restrict__ pg_b,
                 const float* __restrict__ out_w,
                 float*       __restrict__ outp) {
  __shared__ float s_x[2 * 1152];
  __shared__ float s_xg[2 * 192], s_hg[2 * 192];
  __shared__ float s_prev[2 * 256], s_s1[2 * 256], s_s2[2 * 256], s_s3[2 * 256];
  __shared__ float s_s4[2 * 260];
  __shared__ float s_fw[2 * 256], s_fw2[2 * 256];
  __shared__ float s_o1[2 * 256], s_o2[2 * 256], s_o3[2 * 256];
  __shared__ float s_sk[2 * 256], s_sk2[2 * 256];
  __shared__ float s_pl[2 * 68], s_psub[2 * 64], s_pg[2 * 4], s_gain[2 * 2];
  __shared__ float s_out[2 * 64];

  const int tid  = threadIdx.x;
  const int rank = blockIdx.x & 3;
  const int q    = blockIdx.x >> 2;

  // exchange helper: write v to own smem + 3 peers at same offset
  auto exch = [&](float* addr, float v) {
    *addr = v;
    uint32_t a = s2u_(addr);
    st_peer_(mapa_u_(a, (rank + 1) & 3), v);
    st_peer_(mapa_u_(a, (rank + 2) & 3), v);
    st_peer_(mapa_u_(a, (rank + 3) & 3), v);
  };

  if (tid < 512) {
    s_prev[tid] = prev0[q * 512 + tid];
    s_s1[tid] = 0.f; s_s2[tid] = 0.f; s_s3[tid] = 0.f;
  }
  if (tid < 520) s_s4[tid] = 0.f;
  __syncthreads();

  const float gb0 = gain_b[0];
  int per[2];
  const float* condr[2];

  for (int f = 0; f < NFRAMES; ++f) {
    per[0] = periods[(q * 2 + 0) * NFRAMES + f];
    per[1] = periods[(q * 2 + 1) * NFRAMES + f];
    condr[0] = g_cond + (f * NB + q * 2 + 0) * 512;
    condr[1] = g_cond + (f * NB + q * 2 + 1) * 512;

    for (int i = 0; i < 4; ++i) {
      // ---- gain: warp r computes row r (redundant across CTAs)
      if (tid < 64) {
        int row = tid >> 5, l = tid & 31;
        const float* sf = condr[row] + i * 128;
        float d = 0.f;
        for (int k = l; k < 128; k += 32) d = fmaf(sf[k], gain_w[k], d);
#pragma unroll
        for (int o = 16; o; o >>= 1) d += __shfl_xor_sync(0xffffffffu, d, o);
        if (l == 0) {
          float g = expf(d + gb0);
          s_gain[row * 2]     = g;
          s_gain[row * 2 + 1] = 1.0f / (1e-5f + g);
        }
      }
      __syncthreads();

      // ---- pitch gather + psub per row
      if (tid < 136) {
        int row = tid / 68, t = tid % 68;
        int idx = 256 - per[row] + t - 2;
        if (idx >= 256) idx -= per[row];
        s_pl[row * 68 + t] = s_prev[row * 256 + idx] * s_gain[row * 2 + 1];
      } else if (tid >= 256 && tid < 384) {
        int row = (tid - 256) >> 6, t = (tid - 256) & 63;
        s_psub[row * 64 + t] = s_prev[row * 256 + 192 + t] * s_gain[row * 2 + 1];
      }
      __syncthreads();

      // ---- fw input assembly: per row [sf(128), psub(64), pl(68), s4(260), pad]
      for (int idx = tid; idx < 2 * 544; idx += NTHREADS) {
        int row = idx / 544, p = idx % 544;
        float v;
        if (p < 128)       v = condr[row][i * 128 + p];
        else if (p < 192)  v = s_psub[row * 64 + (p - 128)];
        else if (p < 260)  v = s_pl[row * 68 + (p - 192)];
        else if (p < 520)  v = s_s4[row * 260 + (p - 260)];
        else               v = 0.f;
        s_x[row * 1152 + p] = v;
      }
      __syncthreads();
      // s4 <- sif (x[0:260]); stable during gemv
      if (tid < 520) {
        int row = tid / 260, t = tid % 260;
        s_s4[row * 260 + t] = s_x[row * 1152 + t];
      }

      gemv2r<544, 64>(g_wh + OFFH_FW + rank * 544 * 64, s_x, 1152, PART_A);
      __syncthreads();
      if (tid < 128) {
        int row = tid >> 6, jl = tid & 63;
        exch(&s_fw[row * 256 + rank * 64 + jl], tanhf(csum2r(PART_A, 64, row, jl)));
      }
      CLUSTER_SYNC_();

      gemv2r<256, 64>(g_wh + OFFH_FWGLU + rank * 256 * 64, s_fw, 256, PART_A);
      __syncthreads();
      if (tid < 128) {
        int row = tid >> 6, jl = tid & 63;
        int j = rank * 64 + jl;
        float v = s_fw[row * 256 + j] * sigmoidf_(csum2r(PART_A, 64, row, jl));
        exch(&s_fw2[row * 256 + j], v);
      }
      CLUSTER_SYNC_();

      // ---- pg: 8 warps (row, gate) redundant per CTA
      if (tid < 256) {
        int w = tid >> 5, l = tid & 31;
        int row = w >> 2, g = w & 3;
        float d = 0.f;
        for (int k = l; k < 256; k += 32)
          d = fmaf(s_fw2[row * 256 + k], pg_w[g * 256 + k], d);
#pragma unroll
        for (int o = 16; o; o >>= 1) d += __shfl_xor_sync(0xffffffffu, d, o);
        if (l == 0) s_pg[row * 4 + g] = sigmoidf_(d + pg_b[g]) + 1e-5f;
      }
      __syncthreads();

      // ================= GRU + GLU macros =================
#define GRU_STAGE(SRC, OFF_IH, OFF_HH, SSTATE, PGI)                              \
      for (int idx = tid; idx < 2 * 384; idx += NTHREADS) {                      \
        int row = idx / 384, p = idx % 384;                                      \
        float v;                                                                 \
        if (p < 256)       v = SRC[row * 256 + p];                               \
        else if (p < 320)  v = s_pg[row * 4 + PGI] * s_pl[row * 68 + 2 + (p - 256)]; \
        else               v = s_psub[row * 64 + (p - 320)];                     \
        s_x[row * 1152 + p] = v;                                                 \
      }                                                                          \
      __syncthreads();                                                           \
      gemv2r<384, 192>(g_wh + OFF_IH + rank * 384 * 192, s_x, 1152, PART_A);     \
      gemv2r<256, 192>(g_wh + OFF_HH + rank * 256 * 192, SSTATE, 256, PART_B);   \
      __syncthreads();                                                           \
      if (tid < 768) {                                                           \
        int arr = tid / 384, t = tid % 384;                                      \
        int row = t / 192, c = t % 192;                                          \
        if (arr == 0) s_xg[row * 192 + c] = csum2r(PART_A, 192, row, c);         \
        else          s_hg[row * 192 + c] = csum2r(PART_B, 192, row, c);         \
      }                                                                          \
      __syncthreads();                                                           \
      if (tid < 128) {                                                           \
        int row = tid >> 6, sl = tid & 63;                                       \
        float r = sigmoidf_(s_xg[row * 192 + sl]       + s_hg[row * 192 + sl]);  \
        float z = sigmoidf_(s_xg[row * 192 + 64 + sl]  + s_hg[row * 192 + 64 + sl]); \
        float n = tanhf(s_xg[row * 192 + 128 + sl] + r * s_hg[row * 192 + 128 + sl]); \
        int j = rank * 64 + sl;                                                  \
        float v = (1.f - z) * n + z * SSTATE[row * 256 + j];                     \
        exch(&SSTATE[row * 256 + j], v);                                         \
      }                                                                          \
      CLUSTER_SYNC_();

#define GLU_STAGE(OFF_GLU, SSTATE, DST)                                          \
      gemv2r<256, 64>(g_wh + OFF_GLU + rank * 256 * 64, SSTATE, 256, PART_A);    \
      __syncthreads();                                                           \
      if (tid < 128) {                                                           \
        int row = tid >> 6, jl = tid & 63;                                       \
        int j = rank * 64 + jl;                                                  \
        float v = SSTATE[row * 256 + j] * sigmoidf_(csum2r(PART_A, 64, row, jl)); \
        exch(&DST[row * 256 + j], v);                                            \
      }                                                                          \
      CLUSTER_SYNC_();

      GRU_STAGE(s_fw2, OFFH_G1IH, OFFH_G1HH, s_s1, 0)
      GLU_STAGE(OFFH_GLU1, s_s1, s_o1)
      GRU_STAGE(s_o1, OFFH_G2IH, OFFH_G2HH, s_s2, 1)
      GLU_STAGE(OFFH_GLU2, s_s2, s_o2)
      GRU_STAGE(s_o2, OFFH_G3IH, OFFH_G3HH, s_s3, 2)
      GLU_STAGE(OFFH_GLU3, s_s3, s_o3)
#undef GRU_STAGE
#undef GLU_STAGE

      // ---- skip input: per row [o1,o2,o3,fw2,pg3*pl2,psub] = 1152
      for (int idx = tid; idx < 2 * 1152; idx += NTHREADS) {
        int row = idx / 1152, p = idx % 1152;
        float v;
        if (p < 256)        v = s_o1[row * 256 + p];
        else if (p < 512)   v = s_o2[row * 256 + (p - 256)];
        else if (p < 768)   v = s_o3[row * 256 + (p - 512)];
        else if (p < 1024)  v = s_fw2[row * 256 + (p - 768)];
        else if (p < 1088)  v = s_pg[row * 4 + 3] * s_pl[row * 68 + 2 + (p - 1024)];
        else                v = s_psub[row * 64 + (p - 1088)];
        s_x[row * 1152 + p] = v;
      }
      __syncthreads();
      gemv2r<1152, 64>(g_wh + OFFH_SKIP + rank * 1152 * 64, s_x, 1152, PART_A);
      __syncthreads();
      if (tid < 128) {
        int row = tid >> 6, jl = tid & 63;
        exch(&s_sk[row * 256 + rank * 64 + jl], tanhf(csum2r(PART_A, 64, row, jl)));
      }
      CLUSTER_SYNC_();

      gemv2r<256, 64>(g_wh + OFFH_SKIPGLU + rank * 256 * 64, s_sk, 256, PART_A);
      __syncthreads();
      if (tid < 128) {
        int row = tid >> 6, jl = tid & 63;
        int j = rank * 64 + jl;
        float v = s_sk[row * 256 + j] * sigmoidf_(csum2r(PART_A, 64, row, jl));
        exch(&s_sk2[row * 256 + j], v);
      }
      CLUSTER_SYNC_();

      // ---- out: warp w -> output o = rank*16 + (w>>1), row = w&1
      {
        const int w = tid >> 5, l = tid & 31;
        const int o = rank * 16 + (w >> 1), row = w & 1;
        const float4* wr = reinterpret_cast<const float4*>(out_w + o * 256) + l * 2;
        const float4* xr = reinterpret_cast<const float4*>(s_sk2 + row * 256) + l * 2;
        float4 wa = wr[0], wb = wr[1];
        float4 xa = xr[0], xb = xr[1];
        float d = wa.x * xa.x + wa.y * xa.y + wa.z * xa.z + wa.w * xa.w
                + wb.x * xb.x + wb.y * xb.y + wb.z * xb.z + wb.w * xb.w;
#pragma unroll
        for (int oo = 16; oo; oo >>= 1) d += __shfl_xor_sync(0xffffffffu, d, oo);
        if (l == 0) {
          float v = tanhf(d) * s_gain[row * 2];
          exch(&s_out[row * 64 + o], v);
          outp[(q * 2 + row) * 25600 + f * 256 + i * 64 + o] = v;
        }
      }
      CLUSTER_SYNC_();

      // ---- prev = [prev[64:], out] per row
      float pv = 0.f;
      if (tid < 512) {
        int row = tid >> 8, t = tid & 255;
        pv = (t < 192) ? s_prev[row * 256 + t + 64] : s_out[row * 64 + (t - 192)];
      }
      __syncthreads();
      if (tid < 512) s_prev[tid] = pv;
      __syncthreads();
    }
  }
}

// ---------------------------------------------------------------------------
extern "C" void kernel_launch(void* const* d_in, const int* in_sizes, int n_in,
                              void* d_out, int out_size) {
  (void)in_sizes; (void)n_in; (void)out_size;
  const float* features = (const float*)d_in[0];
  const float* gfeat    = (const float*)d_in[1];
  const float* prev     = (const float*)d_in[2];
  const int*   periods  = (const int*)d_in[3];
  const float* cond_w1  = (const float*)d_in[4];
  const float* cond_w2  = (const float*)d_in[5];
  const float* cond_w3  = (const float*)d_in[6];
  const float* gain_w   = (const float*)d_in[7];
  const float* gain_b   = (const float*)d_in[8];
  const float* fw_w     = (const float*)d_in[9];
  const float* fw_glu_w = (const float*)d_in[10];
  const float* pg_w     = (const float*)d_in[11];
  const float* pg_b     = (const float*)d_in[12];
  const float* g1ih     = (const float*)d_in[13];
  const float* g1hh     = (const float*)d_in[14];
  const float* g2ih     = (const float*)d_in[15];
  const float* g2hh     = (const float*)d_in[16];
  const float* g3ih     = (const float*)d_in[17];
  const float* g3hh     = (const float*)d_in[18];
  const float* glu1     = (const float*)d_in[19];
  const float* glu2     = (const float*)d_in[20];
  const float* glu3     = (const float*)d_in[21];
  const float* skip_w   = (const float*)d_in[22];
  const float* skipglu  = (const float*)d_in[23];
  const float* out_w    = (const float*)d_in[24];

  __half* wh = nullptr;
  float*  wc = nullptr;
  cudaGetSymbolAddress((void**)&wh, g_wh);
  cudaGetSymbolAddress((void**)&wc, g_wc);

  auto rg4 = [&](const float* src, int off, int O, int I, int Ipad) {
    int tot = O * Ipad;
    reorg_h4<<<(tot + 255) / 256, 256>>>(src, wh + off, O, I, Ipad);
  };
  auto rgg = [&](const float* src, int off, int I) {
    int tot = 768 * I;
    reorg_gru4<<<(tot + 255) / 256, 256>>>(src, wh + off, I);
  };
  auto tpc = [&](const float* src, int off, int O, int I) {
    int tot = O * I;
    transpose_k<<<(tot + 255) / 256, 256>>>(src, wc + off, O, I);
  };

  rg4(fw_w,     OFFH_FW,      256, 520, 544);
  rg4(fw_glu_w, OFFH_FWGLU,   256, 256, 256);
  rgg(g1ih,     OFFH_G1IH,    384);
  rgg(g1hh,     OFFH_G1HH,    256);
  rgg(g2ih,     OFFH_G2IH,    384);
  rgg(g2hh,     OFFH_G2HH,    256);
  rgg(g3ih,     OFFH_G3IH,    384);
  rgg(g3hh,     OFFH_G3HH,    256);
  rg4(glu1,     OFFH_GLU1,    256, 256, 256);
  rg4(glu2,     OFFH_GLU2,    256, 256, 256);
  rg4(glu3,     OFFH_GLU3,    256, 256, 256);
  rg4(skip_w,   OFFH_SKIP,    256, 1152, 1152);
  rg4(skipglu,  OFFH_SKIPGLU, 256, 256, 256);
  tpc(cond_w1,  OFFC_C1,      336, 336);
  tpc(cond_w2,  OFFC_C2,      336, 336);
  tpc(cond_w3,  OFFC_C3,      512, 336);

  dim3 cg(NB, NFRAMES);
  cond_kernel<<<cg, 256>>>(features, gfeat);

  const int dyn_smem = 2 * 2 * 32 * 192 * (int)sizeof(float);  // 96 KB
  cudaFuncSetAttribute(main_kernel, cudaFuncAttributeMaxDynamicSharedMemorySize, dyn_smem);
  main_kernel<<<128, NTHREADS, dyn_smem>>>(prev, periods, gain_w, gain_b,
                                           pg_w, pg_b, out_w, (float*)d_out);
}